// round 13
// baseline (speedup 1.0000x reference)
#include <cuda_runtime.h>
#include <math.h>

#define FULLMASK 0xffffffffu

#define Bc 8
#define Tc 24
#define Nc 1000
#define Ec 1000
#define F_INc 16
#define C_RAWc 8
#define DMc 32
#define HCc 32
#define PREDc 12
#define LAMc 0.3f
#define EPSc 1e-8f
#define MAXD 64
#define ESTRIDE 24     // padded edge member list stride (int4-aligned)

typedef unsigned long long u64;
typedef unsigned int u32;

// ---------------- scratch (device globals; no allocation) ----------------
__device__ int   g_edge_nodes[Ec * ESTRIDE];
__device__ int   g_edge_cnt[Ec];
__device__ int   g_node_edges[Nc * MAXD];
__device__ int   g_node_deg[Nc];
__device__ float g_feat[Bc * Nc * 16];
__device__ float g_msum[Bc * Ec];
__device__ u32   g_mnU[Bc];
__device__ u32   g_mxU[Bc];
__device__ float g_Wd[Bc * Ec];
__device__ float g_dvi[Bc * Nc];
__device__ float g_ipwc[F_INc * DMc];   // folded ipw @ cw
__device__ float g_ipbc[DMc];           // folded ipb @ cw
__device__ float g_hc[(size_t)Bc * Nc * Tc * HCc];   // conv outputs (LSTM inputs)

// ---------------- math helpers ----------------
__device__ __forceinline__ float sigmf(float x) { return __fdividef(1.f, 1.f + __expf(-x)); }
__device__ __forceinline__ float tanhf_(float x) { return 2.f * sigmf(2.f * x) - 1.f; }
__device__ __forceinline__ float siluf(float x) { return x * sigmf(x); }

__device__ __forceinline__ u32 tf32_of(float f) {
    u32 r; asm("cvt.rna.tf32.f32 %0, %1;" : "=r"(r) : "f"(f)); return r;
}
__device__ __forceinline__ void mma_tf32(float c[4], u32 a0, u32 a1, u32 a2, u32 a3,
                                         u32 b0, u32 b1) {
    asm volatile(
        "mma.sync.aligned.m16n8k8.row.col.f32.tf32.tf32.f32 "
        "{%0,%1,%2,%3}, {%4,%5,%6,%7}, {%8,%9}, {%0,%1,%2,%3};"
        : "+f"(c[0]), "+f"(c[1]), "+f"(c[2]), "+f"(c[3])
        : "r"(a0), "r"(a1), "r"(a2), "r"(a3), "r"(b0), "r"(b1));
}

// ---------------- K1: dynamic features (blocks 0..249) + zero degs / minmax init (250..253) ----------------
__global__ void k_feat_zero(const float* __restrict__ xraw) {
    if (blockIdx.x >= 250) {
        int i = (blockIdx.x - 250) * blockDim.x + threadIdx.x;
        if (i < Nc) g_node_deg[i] = 0;
        if (blockIdx.x == 250 && threadIdx.x < Bc) {
            g_mnU[threadIdx.x] = 0x7F800000u;  // +inf (nonneg-float uint ordering)
            g_mxU[threadIdx.x] = 0u;
        }
        return;
    }
    int idx = blockIdx.x * blockDim.x + threadIdx.x;
    if (idx >= Bc * Nc * C_RAWc) return;
    int c = idx % C_RAWc;
    int n = (idx / C_RAWc) % Nc;
    int b = idx / (C_RAWc * Nc);
    float s1 = 0.f, s2 = 0.f;
    #pragma unroll
    for (int t = 0; t < Tc; t++) {
        float v = xraw[((b * Tc + t) * Nc + n) * C_RAWc + c];
        s1 += v; s2 += v * v;
    }
    float mean = s1 * (1.f / Tc);
    float var = s2 * (1.f / Tc) - mean * mean;
    if (var < 0.f) var = 0.f;
    g_feat[(b * Nc + n) * 16 + c] = mean;
    g_feat[(b * Nc + n) * 16 + C_RAWc + c] = sqrtf(var);
}

// ---------------- K2: per-edge similarity + batch min/max (0..999); edge-list build (1000..1003) ----------------
__global__ void k_sim_build(const int* __restrict__ members,
                            const int* __restrict__ centers,
                            const int* __restrict__ offsets) {
    if (blockIdx.x >= 1000) {
        int e = (blockIdx.x - 1000) * blockDim.x + threadIdx.x;
        if (e >= Ec) return;
        int s = offsets[e], t = offsets[e + 1];
        int list[ESTRIDE];
        int cnt = 0;
        for (int m = s; m < t && cnt < ESTRIDE; m++) {
            int n = members[m];
            bool dup = false;
            for (int k = 0; k < cnt; k++) if (list[k] == n) { dup = true; break; }
            if (!dup) list[cnt++] = n;
        }
        {
            int c = centers[e];
            bool dup = false;
            for (int k = 0; k < cnt; k++) if (list[k] == c) { dup = true; break; }
            if (!dup && cnt < ESTRIDE) list[cnt++] = c;
        }
        g_edge_cnt[e] = cnt;
        for (int k = 0; k < cnt; k++) {
            int n = list[k];
            g_edge_nodes[e * ESTRIDE + k] = n;
            int pos = atomicAdd(&g_node_deg[n], 1);
            if (pos < MAXD) g_node_edges[n * MAXD + pos] = e;
        }
        for (int k = cnt; k < ESTRIDE; k++) g_edge_nodes[e * ESTRIDE + k] = Nc;
        return;
    }
    int gid = blockIdx.x * (blockDim.x >> 5) + (threadIdx.x >> 5);
    if (gid >= Bc * Ec) return;
    int e = gid % Ec;
    int b = gid / Ec;
    int lane = threadIdx.x & 31;
    int s = offsets[e];
    int cntm = offsets[e + 1] - s;
    int cn = centers[e];
    const float4* cf4 = (const float4*)(g_feat + (b * Nc + cn) * 16);
    float4 c0 = cf4[0], c1 = cf4[1], c2 = cf4[2], c3 = cf4[3];
    float cn2 = c0.x*c0.x + c0.y*c0.y + c0.z*c0.z + c0.w*c0.w
              + c1.x*c1.x + c1.y*c1.y + c1.z*c1.z + c1.w*c1.w
              + c2.x*c2.x + c2.y*c2.y + c2.z*c2.z + c2.w*c2.w
              + c3.x*c3.x + c3.y*c3.y + c3.z*c3.z + c3.w*c3.w;
    float cnorm = sqrtf(cn2);
    float acc = 0.f;
    for (int m = lane; m < cntm; m += 32) {
        int n = members[s + m];
        const float4* mf4 = (const float4*)(g_feat + (b * Nc + n) * 16);
        float4 m0 = mf4[0], m1 = mf4[1], m2 = mf4[2], m3 = mf4[3];
        float dot = m0.x*c0.x + m0.y*c0.y + m0.z*c0.z + m0.w*c0.w
                  + m1.x*c1.x + m1.y*c1.y + m1.z*c1.z + m1.w*c1.w
                  + m2.x*c2.x + m2.y*c2.y + m2.z*c2.z + m2.w*c2.w
                  + m3.x*c3.x + m3.y*c3.y + m3.z*c3.z + m3.w*c3.w;
        float mn2 = m0.x*m0.x + m0.y*m0.y + m0.z*m0.z + m0.w*m0.w
                  + m1.x*m1.x + m1.y*m1.y + m1.z*m1.z + m1.w*m1.w
                  + m2.x*m2.x + m2.y*m2.y + m2.z*m2.z + m2.w*m2.w
                  + m3.x*m3.x + m3.y*m3.y + m3.z*m3.z + m3.w*m3.w;
        float sim = dot / (sqrtf(mn2) * cnorm + EPSc);
        acc += fminf(fmaxf(sim, 0.f), 1.f);
    }
    #pragma unroll
    for (int o = 16; o > 0; o >>= 1) acc += __shfl_xor_sync(FULLMASK, acc, o);
    if (lane == 0) {
        float count = (float)cntm;
        if (count < 1.f) count = 1.f;
        float v = acc / count;
        g_msum[b * Ec + e] = v;
        u32 vb = __float_as_uint(v);
        atomicMin(&g_mnU[b], vb);
        atomicMax(&g_mxU[b], vb);
    }
}

// ---------------- sort node edge lists (deterministic gather order) ----------------
__global__ void k_sort_nodes() {
    int n = blockIdx.x * blockDim.x + threadIdx.x;
    if (n >= Nc) return;
    int d = g_node_deg[n];
    if (d > MAXD) d = MAXD;
    g_node_deg[n] = d;
    int* L = g_node_edges + n * MAXD;
    for (int i = 1; i < d; i++) {
        int key = L[i];
        int j = i - 1;
        while (j >= 0 && L[j] > key) { L[j + 1] = L[j]; j--; }
        L[j + 1] = key;
    }
    int d8 = (d + 7) & ~7;
    if (d8 > MAXD) d8 = MAXD;
    for (int i = d; i < d8; i++) L[i] = Ec;  // dummy: smem row 1000 zeroed
}

// ---------------- Wd + dvi, 64 parallel (b, slice) blocks; block 64 = conv fold ----------------
__global__ __launch_bounds__(256) void k_wdf2(const float* __restrict__ W,
                                              const float* __restrict__ ipw,
                                              const float* __restrict__ ipb,
                                              const float* __restrict__ cw) {
    int blk = blockIdx.x;
    int tid = threadIdx.x;
    if (blk < 64) {
        __shared__ float sWd[Ec];
        int b = blk >> 3, part = blk & 7;
        float mn = __uint_as_float(g_mnU[b]);
        float mx = __uint_as_float(g_mxU[b]);
        float inv = __fdividef(1.f, mx - mn + EPSc);
        for (int e = tid; e < Ec; e += 256) {
            float v = (g_msum[b * Ec + e] - mn) * inv;
            sWd[e] = W[e] * (1.f + LAMc * v);
        }
        __syncthreads();
        int s0 = part * 125;
        for (int e = s0 + tid; e < s0 + 125; e += 256)
            g_Wd[b * Ec + e] = sWd[e];
        for (int n = s0 + tid; n < s0 + 125; n += 256) {
            int d = g_node_deg[n];
            const int* L = g_node_edges + n * MAXD;
            float s = 0.f;
            for (int i = 0; i < d; i++) s += sWd[L[i]];
            g_dvi[b * Nc + n] = rsqrtf(fmaxf(s, EPSc));
        }
    } else {
        for (int it = tid; it < F_INc * DMc; it += 256) {
            int k = it >> 5, j = it & 31;
            float s = 0.f;
            #pragma unroll
            for (int f = 0; f < DMc; f++) s += ipw[k * DMc + f] * cw[f * HCc + j];
            g_ipwc[it] = s;
        }
        if (tid < 32) {
            float sb = 0.f;
            #pragma unroll
            for (int f = 0; f < DMc; f++) sb += ipb[f] * cw[f * HCc + tid];
            g_ipbc[tid] = sb;
        }
    }
}

// ---------------- quarter-slice kernel: block per ((b,t), feature-quarter) ----------------
// 32.6KB smem -> ~4 blocks/SM; warps process 4 edges/nodes per access (8-lane groups).
__global__ __launch_bounds__(512) void k_slice4(const float* __restrict__ x,
                                                const float* __restrict__ cbg) {
    extern __shared__ float xs[];          // (Nc+1)*8, reused for edge features
    float* sipw = xs + (Nc + 1) * 8;       // 128: [k*8 + j]
    float* sipb = sipw + 128;              // 8
    int blk = blockIdx.x;
    int bt = blk >> 2;
    int quarter = blk & 3;
    int b = bt / Tc;
    int t = bt % Tc;
    int tid = threadIdx.x;
    int lane = tid & 31, w = tid >> 5;
    int fl = lane & 7;       // feature lane within quarter
    int sel = lane >> 3;     // which of 4 grouped elements
    int h8 = quarter * 8;

    if (tid < 128) {
        int k = tid >> 3, j = tid & 7;
        sipw[tid] = g_ipwc[k * 32 + h8 + j];
    }
    if (tid < 8) sipb[tid] = g_ipbc[h8 + tid];
    __syncthreads();

    // phase 1: ys quarter = dvi * (x @ ipwc_q + ipbc_q); row 1000 zeroed
    const float* xb = x + (size_t)bt * Nc * F_INc;
    for (int i = tid; i < (Nc + 1) * 2; i += 512) {
        int n = i >> 1, q = (i & 1) * 4;
        float a0 = 0.f, a1 = 0.f, a2 = 0.f, a3 = 0.f;
        if (n < Nc) {
            const float* xr = xb + n * F_INc;
            a0 = sipb[q]; a1 = sipb[q + 1]; a2 = sipb[q + 2]; a3 = sipb[q + 3];
            #pragma unroll
            for (int k = 0; k < F_INc; k++) {
                float xv = xr[k];
                a0 += xv * sipw[k * 8 + q];
                a1 += xv * sipw[k * 8 + q + 1];
                a2 += xv * sipw[k * 8 + q + 2];
                a3 += xv * sipw[k * 8 + q + 3];
            }
            float d = g_dvi[b * Nc + n];
            a0 *= d; a1 *= d; a2 *= d; a3 *= d;
        }
        *(float4*)(xs + n * 8 + q) = make_float4(a0, a1, a2, a3);
    }
    __syncthreads();

    // phase 2: edge gather into registers; warp w handles edges [w*64, w*64+64) as 16 quads
    int e_base = w * 64;
    float u_reg[16];
    #pragma unroll
    for (int s = 0; s < 16; s++) {
        int e = e_base + 4 * s + sel;
        float uv = 0.f;
        if (e < Ec) {
            const int4* ip = (const int4*)(g_edge_nodes + e * ESTRIDE);
            int4 a0 = ip[0], a1 = ip[1], a2 = ip[2], a3 = ip[3], a4 = ip[4], a5 = ip[5];
            float p0 = xs[a0.x * 8 + fl] + xs[a1.x * 8 + fl]
                     + xs[a2.x * 8 + fl] + xs[a3.x * 8 + fl]
                     + xs[a4.x * 8 + fl] + xs[a5.x * 8 + fl];
            float p1 = xs[a0.y * 8 + fl] + xs[a1.y * 8 + fl]
                     + xs[a2.y * 8 + fl] + xs[a3.y * 8 + fl]
                     + xs[a4.y * 8 + fl] + xs[a5.y * 8 + fl];
            float p2 = xs[a0.z * 8 + fl] + xs[a1.z * 8 + fl]
                     + xs[a2.z * 8 + fl] + xs[a3.z * 8 + fl]
                     + xs[a4.z * 8 + fl] + xs[a5.z * 8 + fl];
            float p3 = xs[a0.w * 8 + fl] + xs[a1.w * 8 + fl]
                     + xs[a2.w * 8 + fl] + xs[a3.w * 8 + fl]
                     + xs[a4.w * 8 + fl] + xs[a5.w * 8 + fl];
            float sc = __fdividef(g_Wd[b * Ec + e], (float)g_edge_cnt[e]);
            uv = ((p0 + p1) + (p2 + p3)) * sc;
        }
        u_reg[s] = uv;
    }
    __syncthreads();   // all reads of ys complete

    // phase 3: overwrite smem with edge features (+ dummy zero row 1000)
    #pragma unroll
    for (int s = 0; s < 16; s++) {
        int e = e_base + 4 * s + sel;
        if (e < Ec) xs[e * 8 + fl] = u_reg[s];
    }
    if (tid < 8) xs[Nc * 8 + tid] = 0.f;
    __syncthreads();

    // phase 4: node gather + silu -> g_hc quarter; warp handles node quads
    float cbv = cbg[h8 + fl];
    for (int np = w; np < Nc / 4; np += 16) {
        int n = np * 4 + sel;
        int deg = g_node_deg[n];
        int d8 = (deg + 7) & ~7;
        const int* L = g_node_edges + n * MAXD;
        float p0 = 0.f, p1 = 0.f;
        for (int k = 0; k < d8; k += 8) {
            int4 a = *(const int4*)(L + k);
            int4 b2 = *(const int4*)(L + k + 4);
            p0 += xs[a.x * 8 + fl] + xs[a.z * 8 + fl]
                + xs[b2.x * 8 + fl] + xs[b2.z * 8 + fl];
            p1 += xs[a.y * 8 + fl] + xs[a.w * 8 + fl]
                + xs[b2.y * 8 + fl] + xs[b2.w * 8 + fl];
        }
        float z = (p0 + p1) * g_dvi[b * Nc + n] + cbv;
        g_hc[((size_t)(b * Nc + n) * Tc + t) * 32 + h8 + fl] = siluf(z);
    }
}

// ---------------- LSTM: tensor-core recurrence (tf32 2-pass split), 32 rows/block ----------------
#define ASTR 68
#define ZSTR 132
__global__ __launch_bounds__(128) void k_lstm_tc(
    const float* __restrict__ wx, const float* __restrict__ wh,
    const float* __restrict__ lb,
    const float* __restrict__ hw1, const float* __restrict__ hb1,
    const float* __restrict__ hw2, const float* __restrict__ hb2,
    float* __restrict__ out, int Pout) {
    extern __shared__ __align__(16) float sm[];
    float* sAhi = sm;                    // 32*68 = 2176
    float* sAlo = sAhi + 32 * ASTR;      // 2176
    float* zbuf = sAlo + 32 * ASTR;      // 32*132 = 4224
    float* lbS  = zbuf + 32 * ZSTR;      // 128
    float* hw1S = lbS + 128;             // 1024
    float* hb1S = hw1S + 1024;           // 32
    float* hw2S = hb1S + 32;             // 384
    float* hb2S = hw2S + 384;            // 16

    int tid = threadIdx.x;
    int lane = tid & 31, w = tid >> 5;
    int gid = lane >> 2, tig = lane & 3;
    int gblk = w;
    int rb = blockIdx.x * 32;

    for (int i = tid; i < 1024; i += 128) hw1S[i] = hw1[i];
    for (int i = tid; i < 384; i += 128) hw2S[i] = hw2[i];
    if (tid < 128) lbS[tid] = lb[tid];
    if (tid < 32) hb1S[tid] = hb1[tid];
    if (tid < PREDc) hb2S[tid] = hb2[tid];

    u32 bw0[8][4], bw1[8][4];
    #pragma unroll
    for (int ks = 0; ks < 8; ks++) {
        #pragma unroll
        for (int nt = 0; nt < 4; nt++) {
            int col = gblk * 32 + nt * 8 + gid;
            int k0 = ks * 8 + tig;
            int k1 = k0 + 4;
            float f0 = (k0 < 32) ? wx[k0 * 128 + col] : wh[(k0 - 32) * 128 + col];
            float f1 = (k1 < 32) ? wx[k1 * 128 + col] : wh[(k1 - 32) * 128 + col];
            bw0[ks][nt] = tf32_of(f0);
            bw1[ks][nt] = tf32_of(f1);
        }
    }

    int r0 = w * 8;
    float h[8], cst[8];
    #pragma unroll
    for (int q = 0; q < 8; q++) {
        h[q] = 0.f; cst[q] = 0.f;
        int r = r0 + q;
        float hc = g_hc[((size_t)(rb + r) * Tc) * 32 + lane];
        u32 hib = tf32_of(hc);
        float hif = __uint_as_float(hib);
        sAhi[r * ASTR + lane] = hif;
        sAlo[r * ASTR + lane] = hc - hif;
        sAhi[r * ASTR + 32 + lane] = 0.f;
        sAlo[r * ASTR + 32 + lane] = 0.f;
    }
    __syncthreads();

    for (int t = 0; t < Tc; t++) {
        float hcn[8];
        if (t + 1 < Tc) {
            #pragma unroll
            for (int q = 0; q < 8; q++)
                hcn[q] = g_hc[((size_t)(rb + r0 + q) * Tc + t + 1) * 32 + lane];
        }

        float cc[2][4][4];
        #pragma unroll
        for (int mt = 0; mt < 2; mt++) {
            #pragma unroll
            for (int nt = 0; nt < 4; nt++) {
                int col = gblk * 32 + nt * 8 + tig * 2;
                cc[mt][nt][0] = lbS[col];
                cc[mt][nt][1] = lbS[col + 1];
                cc[mt][nt][2] = lbS[col];
                cc[mt][nt][3] = lbS[col + 1];
            }
        }
        #pragma unroll
        for (int ks = 0; ks < 8; ks++) {
            #pragma unroll
            for (int mt = 0; mt < 2; mt++) {
                int row = mt * 16 + gid;
                int ca = ks * 8 + tig;
                u32 a0h = __float_as_uint(sAhi[row * ASTR + ca]);
                u32 a1h = __float_as_uint(sAhi[(row + 8) * ASTR + ca]);
                u32 a2h = __float_as_uint(sAhi[row * ASTR + ca + 4]);
                u32 a3h = __float_as_uint(sAhi[(row + 8) * ASTR + ca + 4]);
                u32 a0l = __float_as_uint(sAlo[row * ASTR + ca]);
                u32 a1l = __float_as_uint(sAlo[(row + 8) * ASTR + ca]);
                u32 a2l = __float_as_uint(sAlo[row * ASTR + ca + 4]);
                u32 a3l = __float_as_uint(sAlo[(row + 8) * ASTR + ca + 4]);
                #pragma unroll
                for (int nt = 0; nt < 4; nt++) {
                    mma_tf32(cc[mt][nt], a0h, a1h, a2h, a3h, bw0[ks][nt], bw1[ks][nt]);
                    mma_tf32(cc[mt][nt], a0l, a1l, a2l, a3l, bw0[ks][nt], bw1[ks][nt]);
                }
            }
        }
        #pragma unroll
        for (int mt = 0; mt < 2; mt++) {
            int row = mt * 16 + gid;
            #pragma unroll
            for (int nt = 0; nt < 4; nt++) {
                int col = gblk * 32 + nt * 8 + tig * 2;
                *(float2*)&zbuf[row * ZSTR + col] = make_float2(cc[mt][nt][0], cc[mt][nt][1]);
                *(float2*)&zbuf[(row + 8) * ZSTR + col] = make_float2(cc[mt][nt][2], cc[mt][nt][3]);
            }
        }
        __syncthreads();

        #pragma unroll
        for (int q = 0; q < 8; q++) {
            int r = r0 + q;
            float zi = zbuf[r * ZSTR + lane];
            float zf = zbuf[r * ZSTR + 32 + lane];
            float zg = zbuf[r * ZSTR + 64 + lane];
            float zo = zbuf[r * ZSTR + 96 + lane];
            float ig = sigmf(zi);
            float fg = sigmf(zf);
            float gg = tanhf_(zg);
            float og = sigmf(zo);
            cst[q] = fg * cst[q] + ig * gg;
            h[q] = og * tanhf_(cst[q]);
            u32 hib = tf32_of(h[q]);
            float hif = __uint_as_float(hib);
            sAhi[r * ASTR + 32 + lane] = hif;
            sAlo[r * ASTR + 32 + lane] = h[q] - hif;
            if (t + 1 < Tc) {
                float hc = hcn[q];
                u32 cb2 = tf32_of(hc);
                float cf2 = __uint_as_float(cb2);
                sAhi[r * ASTR + lane] = cf2;
                sAlo[r * ASTR + lane] = hc - cf2;
            }
        }
        __syncthreads();
    }

    // head: y = silu(h @ hw1 + hb1) @ hw2 + hb2   (warp owns rows r0..r0+8)
    #pragma unroll
    for (int q = 0; q < 8; q++) {
        int row = rb + r0 + q;
        int b = row / Nc;
        int n = row % Nc;
        float a = hb1S[lane];
        #pragma unroll 8
        for (int i = 0; i < 32; i++) {
            float hi = __shfl_sync(FULLMASK, h[q], i);
            a += hi * hw1S[i * 32 + lane];
        }
        float y1 = siluf(a);
        float o = (lane < PREDc) ? hb2S[lane] : 0.f;
        #pragma unroll 8
        for (int j = 0; j < 32; j++) {
            float yj = __shfl_sync(FULLMASK, y1, j);
            if (lane < PREDc) o += yj * hw2S[j * PREDc + lane];
        }
        if (lane < Pout) out[((size_t)b * Pout + lane) * Nc + n] = o;
    }
}

// ---------------- launch ----------------
extern "C" void kernel_launch(void* const* d_in, const int* in_sizes, int n_in,
                              void* d_out, int out_size) {
    const float* x       = (const float*)d_in[0];
    const float* xraw    = (const float*)d_in[1];
    const float* W       = (const float*)d_in[3];
    const int*   members = (const int*)d_in[4];
    const int*   centers = (const int*)d_in[5];
    const int*   offsets = (const int*)d_in[6];
    const float* ipw     = (const float*)d_in[7];
    const float* ipb     = (const float*)d_in[8];
    const float* cw      = (const float*)d_in[9];
    const float* cb      = (const float*)d_in[10];
    const float* wx      = (const float*)d_in[11];
    const float* wh      = (const float*)d_in[12];
    const float* lb      = (const float*)d_in[13];
    const float* hw1     = (const float*)d_in[14];
    const float* hb1     = (const float*)d_in[15];
    const float* hw2     = (const float*)d_in[16];
    const float* hb2     = (const float*)d_in[17];
    float* out = (float*)d_out;
    int Pout = out_size / (Bc * Nc);

    int smem_slice = ((Nc + 1) * 8 + 128 + 8) * sizeof(float);                         // 32576
    int smem_lstm  = (32 * ASTR * 2 + 32 * ZSTR + 128 + 1024 + 32 + 384 + 16) * 4;     // ~41KB
    cudaFuncSetAttribute(k_slice4, cudaFuncAttributeMaxDynamicSharedMemorySize, smem_slice);
    cudaFuncSetAttribute(k_lstm_tc, cudaFuncAttributeMaxDynamicSharedMemorySize, smem_lstm);

    k_feat_zero<<<254, 256>>>(xraw);                       // feat + zero degs + minmax init
    k_sim_build<<<1004, 256>>>(members, centers, offsets); // sim + atomic minmax + edge build
    k_sort_nodes<<<4, 256>>>();
    k_wdf2<<<65, 256>>>(W, ipw, ipb, cw);
    k_slice4<<<Bc * Tc * 4, 512, smem_slice>>>(x, cb);
    k_lstm_tc<<<Bc * Nc / 32, 128, smem_lstm>>>(wx, wh, lb, hw1, hb1, hw2, hb2, out, Pout);
}

// round 14
// speedup vs baseline: 1.0689x; 1.0689x over previous
#include <cuda_runtime.h>
#include <math.h>

#define FULLMASK 0xffffffffu

#define Bc 8
#define Tc 24
#define Nc 1000
#define Ec 1000
#define F_INc 16
#define C_RAWc 8
#define DMc 32
#define HCc 32
#define PREDc 12
#define LAMc 0.3f
#define EPSc 1e-8f
#define MAXD 64
#define ESTRIDE 24     // padded edge member list stride (int4-aligned)

typedef unsigned long long u64;
typedef unsigned int u32;

// ---------------- scratch (device globals; no allocation) ----------------
__device__ int   g_edge_nodes[Ec * ESTRIDE];
__device__ int   g_edge_cnt[Ec];
__device__ int   g_node_edges[Nc * MAXD];
__device__ int   g_node_deg[Nc];
__device__ float g_feat[Bc * Nc * 16];
__device__ float g_msum[Bc * Ec];
__device__ u32   g_mnU[Bc];
__device__ u32   g_mxU[Bc];
__device__ float g_Wd[Bc * Ec];
__device__ float g_dvi[Bc * Nc];
__device__ float g_ipwc[F_INc * DMc];   // folded ipw @ cw
__device__ float g_ipbc[DMc];           // folded ipb @ cw
__device__ float g_hc[(size_t)Bc * Nc * Tc * HCc];   // conv outputs (LSTM inputs)

// ---------------- math helpers ----------------
__device__ __forceinline__ float sigmf(float x) { return __fdividef(1.f, 1.f + __expf(-x)); }
__device__ __forceinline__ float tanhf_(float x) { return 2.f * sigmf(2.f * x) - 1.f; }
__device__ __forceinline__ float siluf(float x) { return x * sigmf(x); }

__device__ __forceinline__ u32 tf32_of(float f) {
    u32 r; asm("cvt.rna.tf32.f32 %0, %1;" : "=r"(r) : "f"(f)); return r;
}
__device__ __forceinline__ void mma_tf32(float c[4], u32 a0, u32 a1, u32 a2, u32 a3,
                                         u32 b0, u32 b1) {
    asm volatile(
        "mma.sync.aligned.m16n8k8.row.col.f32.tf32.tf32.f32 "
        "{%0,%1,%2,%3}, {%4,%5,%6,%7}, {%8,%9}, {%0,%1,%2,%3};"
        : "+f"(c[0]), "+f"(c[1]), "+f"(c[2]), "+f"(c[3])
        : "r"(a0), "r"(a1), "r"(a2), "r"(a3), "r"(b0), "r"(b1));
}

// ---------------- K1: dynamic features (blocks 0..249) + zero degs / minmax init (250..253) ----------------
__global__ void k_feat_zero(const float* __restrict__ xraw) {
    if (blockIdx.x >= 250) {
        int i = (blockIdx.x - 250) * blockDim.x + threadIdx.x;
        if (i < Nc) g_node_deg[i] = 0;
        if (blockIdx.x == 250 && threadIdx.x < Bc) {
            g_mnU[threadIdx.x] = 0x7F800000u;  // +inf (nonneg-float uint ordering)
            g_mxU[threadIdx.x] = 0u;
        }
        return;
    }
    int idx = blockIdx.x * blockDim.x + threadIdx.x;
    if (idx >= Bc * Nc * C_RAWc) return;
    int c = idx % C_RAWc;
    int n = (idx / C_RAWc) % Nc;
    int b = idx / (C_RAWc * Nc);
    float s1 = 0.f, s2 = 0.f;
    #pragma unroll
    for (int t = 0; t < Tc; t++) {
        float v = xraw[((b * Tc + t) * Nc + n) * C_RAWc + c];
        s1 += v; s2 += v * v;
    }
    float mean = s1 * (1.f / Tc);
    float var = s2 * (1.f / Tc) - mean * mean;
    if (var < 0.f) var = 0.f;
    g_feat[(b * Nc + n) * 16 + c] = mean;
    g_feat[(b * Nc + n) * 16 + C_RAWc + c] = sqrtf(var);
}

// ---------------- K2: per-edge similarity + batch min/max (0..999); edge-list build (1000..1003) ----------------
__global__ void k_sim_build(const int* __restrict__ members,
                            const int* __restrict__ centers,
                            const int* __restrict__ offsets) {
    if (blockIdx.x >= 1000) {
        int e = (blockIdx.x - 1000) * blockDim.x + threadIdx.x;
        if (e >= Ec) return;
        int s = offsets[e], t = offsets[e + 1];
        int list[ESTRIDE];
        int cnt = 0;
        for (int m = s; m < t && cnt < ESTRIDE; m++) {
            int n = members[m];
            bool dup = false;
            for (int k = 0; k < cnt; k++) if (list[k] == n) { dup = true; break; }
            if (!dup) list[cnt++] = n;
        }
        {
            int c = centers[e];
            bool dup = false;
            for (int k = 0; k < cnt; k++) if (list[k] == c) { dup = true; break; }
            if (!dup && cnt < ESTRIDE) list[cnt++] = c;
        }
        g_edge_cnt[e] = cnt;
        for (int k = 0; k < cnt; k++) {
            int n = list[k];
            g_edge_nodes[e * ESTRIDE + k] = n;
            int pos = atomicAdd(&g_node_deg[n], 1);
            if (pos < MAXD) g_node_edges[n * MAXD + pos] = e;
        }
        for (int k = cnt; k < ESTRIDE; k++) g_edge_nodes[e * ESTRIDE + k] = Nc;
        return;
    }
    int gid = blockIdx.x * (blockDim.x >> 5) + (threadIdx.x >> 5);
    if (gid >= Bc * Ec) return;
    int e = gid % Ec;
    int b = gid / Ec;
    int lane = threadIdx.x & 31;
    int s = offsets[e];
    int cntm = offsets[e + 1] - s;
    int cn = centers[e];
    const float4* cf4 = (const float4*)(g_feat + (b * Nc + cn) * 16);
    float4 c0 = cf4[0], c1 = cf4[1], c2 = cf4[2], c3 = cf4[3];
    float cn2 = c0.x*c0.x + c0.y*c0.y + c0.z*c0.z + c0.w*c0.w
              + c1.x*c1.x + c1.y*c1.y + c1.z*c1.z + c1.w*c1.w
              + c2.x*c2.x + c2.y*c2.y + c2.z*c2.z + c2.w*c2.w
              + c3.x*c3.x + c3.y*c3.y + c3.z*c3.z + c3.w*c3.w;
    float cnorm = sqrtf(cn2);
    float acc = 0.f;
    for (int m = lane; m < cntm; m += 32) {
        int n = members[s + m];
        const float4* mf4 = (const float4*)(g_feat + (b * Nc + n) * 16);
        float4 m0 = mf4[0], m1 = mf4[1], m2 = mf4[2], m3 = mf4[3];
        float dot = m0.x*c0.x + m0.y*c0.y + m0.z*c0.z + m0.w*c0.w
                  + m1.x*c1.x + m1.y*c1.y + m1.z*c1.z + m1.w*c1.w
                  + m2.x*c2.x + m2.y*c2.y + m2.z*c2.z + m2.w*c2.w
                  + m3.x*c3.x + m3.y*c3.y + m3.z*c3.z + m3.w*c3.w;
        float mn2 = m0.x*m0.x + m0.y*m0.y + m0.z*m0.z + m0.w*m0.w
                  + m1.x*m1.x + m1.y*m1.y + m1.z*m1.z + m1.w*m1.w
                  + m2.x*m2.x + m2.y*m2.y + m2.z*m2.z + m2.w*m2.w
                  + m3.x*m3.x + m3.y*m3.y + m3.z*m3.z + m3.w*m3.w;
        float sim = dot / (sqrtf(mn2) * cnorm + EPSc);
        acc += fminf(fmaxf(sim, 0.f), 1.f);
    }
    #pragma unroll
    for (int o = 16; o > 0; o >>= 1) acc += __shfl_xor_sync(FULLMASK, acc, o);
    if (lane == 0) {
        float count = (float)cntm;
        if (count < 1.f) count = 1.f;
        float v = acc / count;
        g_msum[b * Ec + e] = v;
        u32 vb = __float_as_uint(v);
        atomicMin(&g_mnU[b], vb);
        atomicMax(&g_mxU[b], vb);
    }
}

// ---------------- sort node edge lists (deterministic gather order) ----------------
__global__ void k_sort_nodes() {
    int n = blockIdx.x * blockDim.x + threadIdx.x;
    if (n >= Nc) return;
    int d = g_node_deg[n];
    if (d > MAXD) d = MAXD;
    g_node_deg[n] = d;
    int* L = g_node_edges + n * MAXD;
    for (int i = 1; i < d; i++) {
        int key = L[i];
        int j = i - 1;
        while (j >= 0 && L[j] > key) { L[j + 1] = L[j]; j--; }
        L[j + 1] = key;
    }
    int d8 = (d + 7) & ~7;
    if (d8 > MAXD) d8 = MAXD;
    for (int i = d; i < d8; i++) L[i] = Ec;  // dummy: smem row 1000 zeroed
}

// ---------------- Wd + dvi, 64 parallel (b, slice) blocks; block 64 = conv fold ----------------
__global__ __launch_bounds__(256) void k_wdf2(const float* __restrict__ W,
                                              const float* __restrict__ ipw,
                                              const float* __restrict__ ipb,
                                              const float* __restrict__ cw) {
    int blk = blockIdx.x;
    int tid = threadIdx.x;
    if (blk < 64) {
        __shared__ float sWd[Ec];
        int b = blk >> 3, part = blk & 7;
        float mn = __uint_as_float(g_mnU[b]);
        float mx = __uint_as_float(g_mxU[b]);
        float inv = __fdividef(1.f, mx - mn + EPSc);
        for (int e = tid; e < Ec; e += 256) {
            float v = (g_msum[b * Ec + e] - mn) * inv;
            sWd[e] = W[e] * (1.f + LAMc * v);
        }
        __syncthreads();
        int s0 = part * 125;
        for (int e = s0 + tid; e < s0 + 125; e += 256)
            g_Wd[b * Ec + e] = sWd[e];
        for (int n = s0 + tid; n < s0 + 125; n += 256) {
            int d = g_node_deg[n];
            const int* L = g_node_edges + n * MAXD;
            float s = 0.f;
            for (int i = 0; i < d; i++) s += sWd[L[i]];
            g_dvi[b * Nc + n] = rsqrtf(fmaxf(s, EPSc));
        }
    } else {
        for (int it = tid; it < F_INc * DMc; it += 256) {
            int k = it >> 5, j = it & 31;
            float s = 0.f;
            #pragma unroll
            for (int f = 0; f < DMc; f++) s += ipw[k * DMc + f] * cw[f * HCc + j];
            g_ipwc[it] = s;
        }
        if (tid < 32) {
            float sb = 0.f;
            #pragma unroll
            for (int f = 0; f < DMc; f++) sb += ipb[f] * cw[f * HCc + tid];
            g_ipbc[tid] = sb;
        }
    }
}

// ---------------- half-slice kernel: block per ((b,t), feature-half) ----------------
__global__ __launch_bounds__(512) void k_slice2(const float* __restrict__ x,
                                                const float* __restrict__ cbg) {
    extern __shared__ float xs[];          // (Nc+1)*16, reused for edge features
    float* sipw = xs + (Nc + 1) * 16;      // 256: [k*16 + j]
    float* sipb = sipw + 256;              // 16
    int blk = blockIdx.x;
    int bt = blk >> 1;
    int half = blk & 1;
    int b = bt / Tc;
    int t = bt % Tc;
    int tid = threadIdx.x;
    int lane = tid & 31, w = tid >> 5;
    int fl = lane & 15;
    int sel = lane >> 4;
    int h16 = half * 16;

    if (tid < 256) {
        int k = tid >> 4, j = tid & 15;
        sipw[tid] = g_ipwc[k * 32 + h16 + j];
    }
    if (tid < 16) sipb[tid] = g_ipbc[h16 + tid];
    __syncthreads();

    const float* xb = x + (size_t)bt * Nc * F_INc;
    for (int i = tid; i < (Nc + 1) * 4; i += 512) {
        int n = i >> 2, q = (i & 3) * 4;
        float a0 = 0.f, a1 = 0.f, a2 = 0.f, a3 = 0.f;
        if (n < Nc) {
            const float* xr = xb + n * F_INc;
            a0 = sipb[q]; a1 = sipb[q + 1]; a2 = sipb[q + 2]; a3 = sipb[q + 3];
            #pragma unroll
            for (int k = 0; k < F_INc; k++) {
                float xv = xr[k];
                a0 += xv * sipw[k * 16 + q];
                a1 += xv * sipw[k * 16 + q + 1];
                a2 += xv * sipw[k * 16 + q + 2];
                a3 += xv * sipw[k * 16 + q + 3];
            }
            float d = g_dvi[b * Nc + n];
            a0 *= d; a1 *= d; a2 *= d; a3 *= d;
        }
        *(float4*)(xs + n * 16 + q) = make_float4(a0, a1, a2, a3);
    }
    __syncthreads();

    int e_base = w * 64;
    float u_reg[32];
    #pragma unroll
    for (int s = 0; s < 32; s++) {
        int e = e_base + 2 * s + sel;
        float uv = 0.f;
        if (e < Ec) {
            const int4* ip = (const int4*)(g_edge_nodes + e * ESTRIDE);
            int4 a0 = ip[0], a1 = ip[1], a2 = ip[2], a3 = ip[3], a4 = ip[4], a5 = ip[5];
            float p0 = xs[a0.x * 16 + fl] + xs[a1.x * 16 + fl]
                     + xs[a2.x * 16 + fl] + xs[a3.x * 16 + fl]
                     + xs[a4.x * 16 + fl] + xs[a5.x * 16 + fl];
            float p1 = xs[a0.y * 16 + fl] + xs[a1.y * 16 + fl]
                     + xs[a2.y * 16 + fl] + xs[a3.y * 16 + fl]
                     + xs[a4.y * 16 + fl] + xs[a5.y * 16 + fl];
            float p2 = xs[a0.z * 16 + fl] + xs[a1.z * 16 + fl]
                     + xs[a2.z * 16 + fl] + xs[a3.z * 16 + fl]
                     + xs[a4.z * 16 + fl] + xs[a5.z * 16 + fl];
            float p3 = xs[a0.w * 16 + fl] + xs[a1.w * 16 + fl]
                     + xs[a2.w * 16 + fl] + xs[a3.w * 16 + fl]
                     + xs[a4.w * 16 + fl] + xs[a5.w * 16 + fl];
            float sc = __fdividef(g_Wd[b * Ec + e], (float)g_edge_cnt[e]);
            uv = ((p0 + p1) + (p2 + p3)) * sc;
        }
        u_reg[s] = uv;
    }
    __syncthreads();

    #pragma unroll
    for (int s = 0; s < 32; s++) {
        int e = e_base + 2 * s + sel;
        if (e < Ec) xs[e * 16 + fl] = u_reg[s];
    }
    if (tid < 16) xs[Nc * 16 + tid] = 0.f;
    __syncthreads();

    float cbv = cbg[h16 + fl];
    for (int np = w; np < Nc / 2; np += 16) {
        int n = np * 2 + sel;
        int deg = g_node_deg[n];
        int d8 = (deg + 7) & ~7;
        const int* L = g_node_edges + n * MAXD;
        float p0 = 0.f, p1 = 0.f;
        for (int k = 0; k < d8; k += 8) {
            int4 a = *(const int4*)(L + k);
            int4 b2 = *(const int4*)(L + k + 4);
            p0 += xs[a.x * 16 + fl] + xs[a.z * 16 + fl]
                + xs[b2.x * 16 + fl] + xs[b2.z * 16 + fl];
            p1 += xs[a.y * 16 + fl] + xs[a.w * 16 + fl]
                + xs[b2.y * 16 + fl] + xs[b2.w * 16 + fl];
        }
        float z = (p0 + p1) * g_dvi[b * Nc + n] + cbv;
        g_hc[((size_t)(b * Nc + n) * Tc + t) * 32 + h16 + fl] = siluf(z);
    }
}

// ---------------- LSTM: tensor-core recurrence (tf32 2-pass split), 32 rows/block ----------------
#define ASTR 68
#define ZSTR 132
__global__ __launch_bounds__(128) void k_lstm_tc(
    const float* __restrict__ wx, const float* __restrict__ wh,
    const float* __restrict__ lb,
    const float* __restrict__ hw1, const float* __restrict__ hb1,
    const float* __restrict__ hw2, const float* __restrict__ hb2,
    float* __restrict__ out, int Pout) {
    extern __shared__ __align__(16) float sm[];
    float* sAhi = sm;                    // 32*68 = 2176
    float* sAlo = sAhi + 32 * ASTR;      // 2176
    float* zbuf = sAlo + 32 * ASTR;      // 32*132 = 4224
    float* lbS  = zbuf + 32 * ZSTR;      // 128
    float* hw1S = lbS + 128;             // 1024
    float* hb1S = hw1S + 1024;           // 32
    float* hw2S = hb1S + 32;             // 384
    float* hb2S = hw2S + 384;            // 16

    int tid = threadIdx.x;
    int lane = tid & 31, w = tid >> 5;
    int gid = lane >> 2, tig = lane & 3;
    int gblk = w;
    int rb = blockIdx.x * 32;

    for (int i = tid; i < 1024; i += 128) hw1S[i] = hw1[i];
    for (int i = tid; i < 384; i += 128) hw2S[i] = hw2[i];
    if (tid < 128) lbS[tid] = lb[tid];
    if (tid < 32) hb1S[tid] = hb1[tid];
    if (tid < PREDc) hb2S[tid] = hb2[tid];

    u32 bw0[8][4], bw1[8][4];
    #pragma unroll
    for (int ks = 0; ks < 8; ks++) {
        #pragma unroll
        for (int nt = 0; nt < 4; nt++) {
            int col = gblk * 32 + nt * 8 + gid;
            int k0 = ks * 8 + tig;
            int k1 = k0 + 4;
            float f0 = (k0 < 32) ? wx[k0 * 128 + col] : wh[(k0 - 32) * 128 + col];
            float f1 = (k1 < 32) ? wx[k1 * 128 + col] : wh[(k1 - 32) * 128 + col];
            bw0[ks][nt] = tf32_of(f0);
            bw1[ks][nt] = tf32_of(f1);
        }
    }

    int r0 = w * 8;
    float h[8], cst[8];
    #pragma unroll
    for (int q = 0; q < 8; q++) {
        h[q] = 0.f; cst[q] = 0.f;
        int r = r0 + q;
        float hc = g_hc[((size_t)(rb + r) * Tc) * 32 + lane];
        u32 hib = tf32_of(hc);
        float hif = __uint_as_float(hib);
        sAhi[r * ASTR + lane] = hif;
        sAlo[r * ASTR + lane] = hc - hif;
        sAhi[r * ASTR + 32 + lane] = 0.f;
        sAlo[r * ASTR + 32 + lane] = 0.f;
    }
    __syncthreads();

    for (int t = 0; t < Tc; t++) {
        float hcn[8];
        if (t + 1 < Tc) {
            #pragma unroll
            for (int q = 0; q < 8; q++)
                hcn[q] = g_hc[((size_t)(rb + r0 + q) * Tc + t + 1) * 32 + lane];
        }

        float cc[2][4][4];
        #pragma unroll
        for (int mt = 0; mt < 2; mt++) {
            #pragma unroll
            for (int nt = 0; nt < 4; nt++) {
                int col = gblk * 32 + nt * 8 + tig * 2;
                cc[mt][nt][0] = lbS[col];
                cc[mt][nt][1] = lbS[col + 1];
                cc[mt][nt][2] = lbS[col];
                cc[mt][nt][3] = lbS[col + 1];
            }
        }
        #pragma unroll
        for (int ks = 0; ks < 8; ks++) {
            #pragma unroll
            for (int mt = 0; mt < 2; mt++) {
                int row = mt * 16 + gid;
                int ca = ks * 8 + tig;
                u32 a0h = __float_as_uint(sAhi[row * ASTR + ca]);
                u32 a1h = __float_as_uint(sAhi[(row + 8) * ASTR + ca]);
                u32 a2h = __float_as_uint(sAhi[row * ASTR + ca + 4]);
                u32 a3h = __float_as_uint(sAhi[(row + 8) * ASTR + ca + 4]);
                u32 a0l = __float_as_uint(sAlo[row * ASTR + ca]);
                u32 a1l = __float_as_uint(sAlo[(row + 8) * ASTR + ca]);
                u32 a2l = __float_as_uint(sAlo[row * ASTR + ca + 4]);
                u32 a3l = __float_as_uint(sAlo[(row + 8) * ASTR + ca + 4]);
                #pragma unroll
                for (int nt = 0; nt < 4; nt++) {
                    mma_tf32(cc[mt][nt], a0h, a1h, a2h, a3h, bw0[ks][nt], bw1[ks][nt]);
                    mma_tf32(cc[mt][nt], a0l, a1l, a2l, a3l, bw0[ks][nt], bw1[ks][nt]);
                }
            }
        }
        #pragma unroll
        for (int mt = 0; mt < 2; mt++) {
            int row = mt * 16 + gid;
            #pragma unroll
            for (int nt = 0; nt < 4; nt++) {
                int col = gblk * 32 + nt * 8 + tig * 2;
                *(float2*)&zbuf[row * ZSTR + col] = make_float2(cc[mt][nt][0], cc[mt][nt][1]);
                *(float2*)&zbuf[(row + 8) * ZSTR + col] = make_float2(cc[mt][nt][2], cc[mt][nt][3]);
            }
        }
        __syncthreads();

        #pragma unroll
        for (int q = 0; q < 8; q++) {
            int r = r0 + q;
            float zi = zbuf[r * ZSTR + lane];
            float zf = zbuf[r * ZSTR + 32 + lane];
            float zg = zbuf[r * ZSTR + 64 + lane];
            float zo = zbuf[r * ZSTR + 96 + lane];
            float ig = sigmf(zi);
            float fg = sigmf(zf);
            float gg = tanhf_(zg);
            float og = sigmf(zo);
            cst[q] = fg * cst[q] + ig * gg;
            h[q] = og * tanhf_(cst[q]);
            u32 hib = tf32_of(h[q]);
            float hif = __uint_as_float(hib);
            sAhi[r * ASTR + 32 + lane] = hif;
            sAlo[r * ASTR + 32 + lane] = h[q] - hif;
            if (t + 1 < Tc) {
                float hc = hcn[q];
                u32 cb2 = tf32_of(hc);
                float cf2 = __uint_as_float(cb2);
                sAhi[r * ASTR + lane] = cf2;
                sAlo[r * ASTR + lane] = hc - cf2;
            }
        }
        __syncthreads();
    }

    // head: y = silu(h @ hw1 + hb1) @ hw2 + hb2   (warp owns rows r0..r0+8)
    #pragma unroll
    for (int q = 0; q < 8; q++) {
        int row = rb + r0 + q;
        int b = row / Nc;
        int n = row % Nc;
        float a = hb1S[lane];
        #pragma unroll 8
        for (int i = 0; i < 32; i++) {
            float hi = __shfl_sync(FULLMASK, h[q], i);
            a += hi * hw1S[i * 32 + lane];
        }
        float y1 = siluf(a);
        float o = (lane < PREDc) ? hb2S[lane] : 0.f;
        #pragma unroll 8
        for (int j = 0; j < 32; j++) {
            float yj = __shfl_sync(FULLMASK, y1, j);
            if (lane < PREDc) o += yj * hw2S[j * PREDc + lane];
        }
        if (lane < Pout) out[((size_t)b * Pout + lane) * Nc + n] = o;
    }
}

// ---------------- launch ----------------
extern "C" void kernel_launch(void* const* d_in, const int* in_sizes, int n_in,
                              void* d_out, int out_size) {
    const float* x       = (const float*)d_in[0];
    const float* xraw    = (const float*)d_in[1];
    const float* W       = (const float*)d_in[3];
    const int*   members = (const int*)d_in[4];
    const int*   centers = (const int*)d_in[5];
    const int*   offsets = (const int*)d_in[6];
    const float* ipw     = (const float*)d_in[7];
    const float* ipb     = (const float*)d_in[8];
    const float* cw      = (const float*)d_in[9];
    const float* cb      = (const float*)d_in[10];
    const float* wx      = (const float*)d_in[11];
    const float* wh      = (const float*)d_in[12];
    const float* lb      = (const float*)d_in[13];
    const float* hw1     = (const float*)d_in[14];
    const float* hb1     = (const float*)d_in[15];
    const float* hw2     = (const float*)d_in[16];
    const float* hb2     = (const float*)d_in[17];
    float* out = (float*)d_out;
    int Pout = out_size / (Bc * Nc);

    int smem_slice = ((Nc + 1) * 16 + 256 + 16) * sizeof(float);                       // 65152
    int smem_lstm  = (32 * ASTR * 2 + 32 * ZSTR + 128 + 1024 + 32 + 384 + 16) * 4;     // ~41KB
    cudaFuncSetAttribute(k_slice2, cudaFuncAttributeMaxDynamicSharedMemorySize, smem_slice);
    cudaFuncSetAttribute(k_lstm_tc, cudaFuncAttributeMaxDynamicSharedMemorySize, smem_lstm);

    k_feat_zero<<<254, 256>>>(xraw);                       // feat + zero degs + minmax init
    k_sim_build<<<1004, 256>>>(members, centers, offsets); // sim + atomic minmax + edge build
    k_sort_nodes<<<4, 256>>>();
    k_wdf2<<<65, 256>>>(W, ipw, ipb, cw);
    k_slice2<<<Bc * Tc * 2, 512, smem_slice>>>(x, cb);
    k_lstm_tc<<<Bc * Nc / 32, 128, smem_lstm>>>(wx, wh, lb, hw1, hb1, hw2, hb2, out, Pout);
}

// round 15
// speedup vs baseline: 1.1064x; 1.0352x over previous
#include <cuda_runtime.h>
#include <math.h>

#define FULLMASK 0xffffffffu

#define Bc 8
#define Tc 24
#define Nc 1000
#define Ec 1000
#define F_INc 16
#define C_RAWc 8
#define DMc 32
#define HCc 32
#define PREDc 12
#define LAMc 0.3f
#define EPSc 1e-8f
#define MAXD 64
#define ESTRIDE 24     // padded edge member list stride (int4-aligned)

typedef unsigned long long u64;
typedef unsigned int u32;

// ---------------- scratch (device globals; no allocation) ----------------
__device__ int   g_edge_nodes[Ec * ESTRIDE];
__device__ int   g_edge_cnt[Ec];
__device__ int   g_node_edges[Nc * MAXD];
__device__ int   g_node_deg[Nc];
__device__ float g_feat[Bc * Nc * 16];
__device__ float g_msum[Bc * Ec];
__device__ u32   g_mnU[Bc];
__device__ u32   g_mxU[Bc];
__device__ float g_Wd[Bc * Ec];
__device__ float g_dvi[Bc * Nc];
__device__ float g_ipwc[F_INc * DMc];   // folded ipw @ cw
__device__ float g_ipbc[DMc];           // folded ipb @ cw
__device__ float g_hc[(size_t)Bc * Nc * Tc * HCc];   // conv outputs (LSTM inputs)

// ---------------- math helpers ----------------
__device__ __forceinline__ float sigmf(float x) { return __fdividef(1.f, 1.f + __expf(-x)); }
__device__ __forceinline__ float tanhf_(float x) { return 2.f * sigmf(2.f * x) - 1.f; }
__device__ __forceinline__ float siluf(float x) { return x * sigmf(x); }

__device__ __forceinline__ u32 tf32_of(float f) {
    u32 r; asm("cvt.rna.tf32.f32 %0, %1;" : "=r"(r) : "f"(f)); return r;
}
__device__ __forceinline__ void mma_tf32(float c[4], u32 a0, u32 a1, u32 a2, u32 a3,
                                         u32 b0, u32 b1) {
    asm volatile(
        "mma.sync.aligned.m16n8k8.row.col.f32.tf32.tf32.f32 "
        "{%0,%1,%2,%3}, {%4,%5,%6,%7}, {%8,%9}, {%0,%1,%2,%3};"
        : "+f"(c[0]), "+f"(c[1]), "+f"(c[2]), "+f"(c[3])
        : "r"(a0), "r"(a1), "r"(a2), "r"(a3), "r"(b0), "r"(b1));
}

// ---------------- K1: dynamic features (blocks 0..249) + zero degs / minmax init (250..253) ----------------
__global__ void k_feat_zero(const float* __restrict__ xraw) {
    if (blockIdx.x >= 250) {
        int i = (blockIdx.x - 250) * blockDim.x + threadIdx.x;
        if (i < Nc) g_node_deg[i] = 0;
        if (blockIdx.x == 250 && threadIdx.x < Bc) {
            g_mnU[threadIdx.x] = 0x7F800000u;  // +inf (nonneg-float uint ordering)
            g_mxU[threadIdx.x] = 0u;
        }
        return;
    }
    int idx = blockIdx.x * blockDim.x + threadIdx.x;
    if (idx >= Bc * Nc * C_RAWc) return;
    int c = idx % C_RAWc;
    int n = (idx / C_RAWc) % Nc;
    int b = idx / (C_RAWc * Nc);
    float s1 = 0.f, s2 = 0.f;
    #pragma unroll
    for (int t = 0; t < Tc; t++) {
        float v = xraw[((b * Tc + t) * Nc + n) * C_RAWc + c];
        s1 += v; s2 += v * v;
    }
    float mean = s1 * (1.f / Tc);
    float var = s2 * (1.f / Tc) - mean * mean;
    if (var < 0.f) var = 0.f;
    g_feat[(b * Nc + n) * 16 + c] = mean;
    g_feat[(b * Nc + n) * 16 + C_RAWc + c] = sqrtf(var);
}

// ---------------- K2: per-edge similarity + batch min/max (0..999); edge-list build (1000..1003) ----------------
__global__ void k_sim_build(const int* __restrict__ members,
                            const int* __restrict__ centers,
                            const int* __restrict__ offsets) {
    if (blockIdx.x >= 1000) {
        int e = (blockIdx.x - 1000) * blockDim.x + threadIdx.x;
        if (e >= Ec) return;
        int s = offsets[e], t = offsets[e + 1];
        int list[ESTRIDE];
        int cnt = 0;
        for (int m = s; m < t && cnt < ESTRIDE; m++) {
            int n = members[m];
            bool dup = false;
            for (int k = 0; k < cnt; k++) if (list[k] == n) { dup = true; break; }
            if (!dup) list[cnt++] = n;
        }
        {
            int c = centers[e];
            bool dup = false;
            for (int k = 0; k < cnt; k++) if (list[k] == c) { dup = true; break; }
            if (!dup && cnt < ESTRIDE) list[cnt++] = c;
        }
        g_edge_cnt[e] = cnt;
        for (int k = 0; k < cnt; k++) {
            int n = list[k];
            g_edge_nodes[e * ESTRIDE + k] = n;
            int pos = atomicAdd(&g_node_deg[n], 1);
            if (pos < MAXD) g_node_edges[n * MAXD + pos] = e;
        }
        for (int k = cnt; k < ESTRIDE; k++) g_edge_nodes[e * ESTRIDE + k] = Nc;
        return;
    }
    int gid = blockIdx.x * (blockDim.x >> 5) + (threadIdx.x >> 5);
    if (gid >= Bc * Ec) return;
    int e = gid % Ec;
    int b = gid / Ec;
    int lane = threadIdx.x & 31;
    int s = offsets[e];
    int cntm = offsets[e + 1] - s;
    int cn = centers[e];
    const float4* cf4 = (const float4*)(g_feat + (b * Nc + cn) * 16);
    float4 c0 = cf4[0], c1 = cf4[1], c2 = cf4[2], c3 = cf4[3];
    float cn2 = c0.x*c0.x + c0.y*c0.y + c0.z*c0.z + c0.w*c0.w
              + c1.x*c1.x + c1.y*c1.y + c1.z*c1.z + c1.w*c1.w
              + c2.x*c2.x + c2.y*c2.y + c2.z*c2.z + c2.w*c2.w
              + c3.x*c3.x + c3.y*c3.y + c3.z*c3.z + c3.w*c3.w;
    float cnorm = sqrtf(cn2);
    float acc = 0.f;
    for (int m = lane; m < cntm; m += 32) {
        int n = members[s + m];
        const float4* mf4 = (const float4*)(g_feat + (b * Nc + n) * 16);
        float4 m0 = mf4[0], m1 = mf4[1], m2 = mf4[2], m3 = mf4[3];
        float dot = m0.x*c0.x + m0.y*c0.y + m0.z*c0.z + m0.w*c0.w
                  + m1.x*c1.x + m1.y*c1.y + m1.z*c1.z + m1.w*c1.w
                  + m2.x*c2.x + m2.y*c2.y + m2.z*c2.z + m2.w*c2.w
                  + m3.x*c3.x + m3.y*c3.y + m3.z*c3.z + m3.w*c3.w;
        float mn2 = m0.x*m0.x + m0.y*m0.y + m0.z*m0.z + m0.w*m0.w
                  + m1.x*m1.x + m1.y*m1.y + m1.z*m1.z + m1.w*m1.w
                  + m2.x*m2.x + m2.y*m2.y + m2.z*m2.z + m2.w*m2.w
                  + m3.x*m3.x + m3.y*m3.y + m3.z*m3.z + m3.w*m3.w;
        float sim = dot / (sqrtf(mn2) * cnorm + EPSc);
        acc += fminf(fmaxf(sim, 0.f), 1.f);
    }
    #pragma unroll
    for (int o = 16; o > 0; o >>= 1) acc += __shfl_xor_sync(FULLMASK, acc, o);
    if (lane == 0) {
        float count = (float)cntm;
        if (count < 1.f) count = 1.f;
        float v = acc / count;
        g_msum[b * Ec + e] = v;
        u32 vb = __float_as_uint(v);
        atomicMin(&g_mnU[b], vb);
        atomicMax(&g_mxU[b], vb);
    }
}

// ---------------- sort node edge lists (deterministic gather order) ----------------
__global__ void k_sort_nodes() {
    int n = blockIdx.x * blockDim.x + threadIdx.x;
    if (n >= Nc) return;
    int d = g_node_deg[n];
    if (d > MAXD) d = MAXD;
    g_node_deg[n] = d;
    int* L = g_node_edges + n * MAXD;
    for (int i = 1; i < d; i++) {
        int key = L[i];
        int j = i - 1;
        while (j >= 0 && L[j] > key) { L[j + 1] = L[j]; j--; }
        L[j + 1] = key;
    }
    int d8 = (d + 7) & ~7;
    if (d8 > MAXD) d8 = MAXD;
    for (int i = d; i < d8; i++) L[i] = Ec;  // dummy: smem row 1000 zeroed
}

// ---------------- Wd + dvi, 64 parallel (b, slice) blocks; block 64 = conv fold ----------------
__global__ __launch_bounds__(256) void k_wdf2(const float* __restrict__ W,
                                              const float* __restrict__ ipw,
                                              const float* __restrict__ ipb,
                                              const float* __restrict__ cw) {
    int blk = blockIdx.x;
    int tid = threadIdx.x;
    if (blk < 64) {
        __shared__ float sWd[Ec];
        int b = blk >> 3, part = blk & 7;
        float mn = __uint_as_float(g_mnU[b]);
        float mx = __uint_as_float(g_mxU[b]);
        float inv = __fdividef(1.f, mx - mn + EPSc);
        for (int e = tid; e < Ec; e += 256) {
            float v = (g_msum[b * Ec + e] - mn) * inv;
            sWd[e] = W[e] * (1.f + LAMc * v);
        }
        __syncthreads();
        int s0 = part * 125;
        for (int e = s0 + tid; e < s0 + 125; e += 256)
            g_Wd[b * Ec + e] = sWd[e];
        for (int n = s0 + tid; n < s0 + 125; n += 256) {
            int d = g_node_deg[n];
            const int* L = g_node_edges + n * MAXD;
            float s = 0.f;
            for (int i = 0; i < d; i++) s += sWd[L[i]];
            g_dvi[b * Nc + n] = rsqrtf(fmaxf(s, EPSc));
        }
    } else {
        for (int it = tid; it < F_INc * DMc; it += 256) {
            int k = it >> 5, j = it & 31;
            float s = 0.f;
            #pragma unroll
            for (int f = 0; f < DMc; f++) s += ipw[k * DMc + f] * cw[f * HCc + j];
            g_ipwc[it] = s;
        }
        if (tid < 32) {
            float sb = 0.f;
            #pragma unroll
            for (int f = 0; f < DMc; f++) sb += ipb[f] * cw[f * HCc + tid];
            g_ipbc[tid] = sb;
        }
    }
}

// ---------------- half-slice kernel: block per ((b,t), feature-half) ----------------
__global__ __launch_bounds__(512) void k_slice2(const float* __restrict__ x,
                                                const float* __restrict__ cbg) {
    extern __shared__ float xs[];          // (Nc+1)*16, reused for edge features
    float* sipw = xs + (Nc + 1) * 16;      // 256: [k*16 + j]
    float* sipb = sipw + 256;              // 16
    int blk = blockIdx.x;
    int bt = blk >> 1;
    int half = blk & 1;
    int b = bt / Tc;
    int t = bt % Tc;
    int tid = threadIdx.x;
    int lane = tid & 31, w = tid >> 5;
    int fl = lane & 15;
    int sel = lane >> 4;
    int h16 = half * 16;

    if (tid < 256) {
        int k = tid >> 4, j = tid & 15;
        sipw[tid] = g_ipwc[k * 32 + h16 + j];
    }
    if (tid < 16) sipb[tid] = g_ipbc[h16 + tid];
    __syncthreads();

    const float* xb = x + (size_t)bt * Nc * F_INc;
    for (int i = tid; i < (Nc + 1) * 4; i += 512) {
        int n = i >> 2, q = (i & 3) * 4;
        float a0 = 0.f, a1 = 0.f, a2 = 0.f, a3 = 0.f;
        if (n < Nc) {
            const float* xr = xb + n * F_INc;
            a0 = sipb[q]; a1 = sipb[q + 1]; a2 = sipb[q + 2]; a3 = sipb[q + 3];
            #pragma unroll
            for (int k = 0; k < F_INc; k++) {
                float xv = xr[k];
                a0 += xv * sipw[k * 16 + q];
                a1 += xv * sipw[k * 16 + q + 1];
                a2 += xv * sipw[k * 16 + q + 2];
                a3 += xv * sipw[k * 16 + q + 3];
            }
            float d = g_dvi[b * Nc + n];
            a0 *= d; a1 *= d; a2 *= d; a3 *= d;
        }
        *(float4*)(xs + n * 16 + q) = make_float4(a0, a1, a2, a3);
    }
    __syncthreads();

    int e_base = w * 64;
    float u_reg[32];
    #pragma unroll
    for (int s = 0; s < 32; s++) {
        int e = e_base + 2 * s + sel;
        float uv = 0.f;
        if (e < Ec) {
            const int4* ip = (const int4*)(g_edge_nodes + e * ESTRIDE);
            int4 a0 = ip[0], a1 = ip[1], a2 = ip[2], a3 = ip[3], a4 = ip[4], a5 = ip[5];
            float p0 = xs[a0.x * 16 + fl] + xs[a1.x * 16 + fl]
                     + xs[a2.x * 16 + fl] + xs[a3.x * 16 + fl]
                     + xs[a4.x * 16 + fl] + xs[a5.x * 16 + fl];
            float p1 = xs[a0.y * 16 + fl] + xs[a1.y * 16 + fl]
                     + xs[a2.y * 16 + fl] + xs[a3.y * 16 + fl]
                     + xs[a4.y * 16 + fl] + xs[a5.y * 16 + fl];
            float p2 = xs[a0.z * 16 + fl] + xs[a1.z * 16 + fl]
                     + xs[a2.z * 16 + fl] + xs[a3.z * 16 + fl]
                     + xs[a4.z * 16 + fl] + xs[a5.z * 16 + fl];
            float p3 = xs[a0.w * 16 + fl] + xs[a1.w * 16 + fl]
                     + xs[a2.w * 16 + fl] + xs[a3.w * 16 + fl]
                     + xs[a4.w * 16 + fl] + xs[a5.w * 16 + fl];
            float sc = __fdividef(g_Wd[b * Ec + e], (float)g_edge_cnt[e]);
            uv = ((p0 + p1) + (p2 + p3)) * sc;
        }
        u_reg[s] = uv;
    }
    __syncthreads();

    #pragma unroll
    for (int s = 0; s < 32; s++) {
        int e = e_base + 2 * s + sel;
        if (e < Ec) xs[e * 16 + fl] = u_reg[s];
    }
    if (tid < 16) xs[Nc * 16 + tid] = 0.f;
    __syncthreads();

    float cbv = cbg[h16 + fl];
    for (int np = w; np < Nc / 2; np += 16) {
        int n = np * 2 + sel;
        int deg = g_node_deg[n];
        int d8 = (deg + 7) & ~7;
        const int* L = g_node_edges + n * MAXD;
        float p0 = 0.f, p1 = 0.f;
        for (int k = 0; k < d8; k += 8) {
            int4 a = *(const int4*)(L + k);
            int4 b2 = *(const int4*)(L + k + 4);
            p0 += xs[a.x * 16 + fl] + xs[a.z * 16 + fl]
                + xs[b2.x * 16 + fl] + xs[b2.z * 16 + fl];
            p1 += xs[a.y * 16 + fl] + xs[a.w * 16 + fl]
                + xs[b2.y * 16 + fl] + xs[b2.w * 16 + fl];
        }
        float z = (p0 + p1) * g_dvi[b * Nc + n] + cbv;
        g_hc[((size_t)(b * Nc + n) * Tc + t) * 32 + h16 + fl] = siluf(z);
    }
}

// ---------------- LSTM: tensor-core recurrence (tf32 2-pass split), 16 rows/block ----------------
// block = 16 rows, 4 warps; warp g: gate-block cols [g*32,+32), single M=16 mma tile.
// State: warp w owns rows [w*4, w*4+4), lane = hidden index.
#define ASTR 68
#define ZSTR 132
__global__ __launch_bounds__(128) void k_lstm_tc(
    const float* __restrict__ wx, const float* __restrict__ wh,
    const float* __restrict__ lb,
    const float* __restrict__ hw1, const float* __restrict__ hb1,
    const float* __restrict__ hw2, const float* __restrict__ hb2,
    float* __restrict__ out, int Pout) {
    extern __shared__ __align__(16) float sm[];
    float* sAhi = sm;                    // 16*68 = 1088
    float* sAlo = sAhi + 16 * ASTR;      // 1088
    float* zbuf = sAlo + 16 * ASTR;      // 16*132 = 2112
    float* lbS  = zbuf + 16 * ZSTR;      // 128
    float* hw1S = lbS + 128;             // 1024
    float* hb1S = hw1S + 1024;           // 32
    float* hw2S = hb1S + 32;             // 384
    float* hb2S = hw2S + 384;            // 16

    int tid = threadIdx.x;
    int lane = tid & 31, w = tid >> 5;
    int gid = lane >> 2, tig = lane & 3;
    int gblk = w;
    int rb = blockIdx.x * 16;

    for (int i = tid; i < 1024; i += 128) hw1S[i] = hw1[i];
    for (int i = tid; i < 384; i += 128) hw2S[i] = hw2[i];
    if (tid < 128) lbS[tid] = lb[tid];
    if (tid < 32) hb1S[tid] = hb1[tid];
    if (tid < PREDc) hb2S[tid] = hb2[tid];

    // stationary weights: B[k][n] = [wx;wh], warp's slice cols [gblk*32, +32)
    u32 bw0[8][4], bw1[8][4];
    #pragma unroll
    for (int ks = 0; ks < 8; ks++) {
        #pragma unroll
        for (int nt = 0; nt < 4; nt++) {
            int col = gblk * 32 + nt * 8 + gid;
            int k0 = ks * 8 + tig;
            int k1 = k0 + 4;
            float f0 = (k0 < 32) ? wx[k0 * 128 + col] : wh[(k0 - 32) * 128 + col];
            float f1 = (k1 < 32) ? wx[k1 * 128 + col] : wh[(k1 - 32) * 128 + col];
            bw0[ks][nt] = tf32_of(f0);
            bw1[ks][nt] = tf32_of(f1);
        }
    }

    // init state + fill sA for t=0 (warp owns rows [w*4, w*4+4), lane = hidden idx)
    int r0 = w * 4;
    float h[4], cst[4];
    #pragma unroll
    for (int q = 0; q < 4; q++) {
        h[q] = 0.f; cst[q] = 0.f;
        int r = r0 + q;
        float hc = g_hc[((size_t)(rb + r) * Tc) * 32 + lane];
        u32 hib = tf32_of(hc);
        float hif = __uint_as_float(hib);
        sAhi[r * ASTR + lane] = hif;
        sAlo[r * ASTR + lane] = hc - hif;
        sAhi[r * ASTR + 32 + lane] = 0.f;
        sAlo[r * ASTR + 32 + lane] = 0.f;
    }
    __syncthreads();

    for (int t = 0; t < Tc; t++) {
        // prefetch hc(t+1) for owned rows (hidden under mma phase)
        float hcn[4];
        if (t + 1 < Tc) {
            #pragma unroll
            for (int q = 0; q < 4; q++)
                hcn[q] = g_hc[((size_t)(rb + r0 + q) * Tc + t + 1) * 32 + lane];
        }

        // mma phase: z = [hc;h] @ W + lb  (2-pass hi/lo split), single M=16 tile
        float cc[4][4];
        #pragma unroll
        for (int nt = 0; nt < 4; nt++) {
            int col = gblk * 32 + nt * 8 + tig * 2;
            cc[nt][0] = lbS[col];
            cc[nt][1] = lbS[col + 1];
            cc[nt][2] = lbS[col];
            cc[nt][3] = lbS[col + 1];
        }
        #pragma unroll
        for (int ks = 0; ks < 8; ks++) {
            int ca = ks * 8 + tig;
            u32 a0h = __float_as_uint(sAhi[gid * ASTR + ca]);
            u32 a1h = __float_as_uint(sAhi[(gid + 8) * ASTR + ca]);
            u32 a2h = __float_as_uint(sAhi[gid * ASTR + ca + 4]);
            u32 a3h = __float_as_uint(sAhi[(gid + 8) * ASTR + ca + 4]);
            u32 a0l = __float_as_uint(sAlo[gid * ASTR + ca]);
            u32 a1l = __float_as_uint(sAlo[(gid + 8) * ASTR + ca]);
            u32 a2l = __float_as_uint(sAlo[gid * ASTR + ca + 4]);
            u32 a3l = __float_as_uint(sAlo[(gid + 8) * ASTR + ca + 4]);
            #pragma unroll
            for (int nt = 0; nt < 4; nt++) {
                mma_tf32(cc[nt], a0h, a1h, a2h, a3h, bw0[ks][nt], bw1[ks][nt]);
                mma_tf32(cc[nt], a0l, a1l, a2l, a3l, bw0[ks][nt], bw1[ks][nt]);
            }
        }
        // store z to zbuf
        #pragma unroll
        for (int nt = 0; nt < 4; nt++) {
            int col = gblk * 32 + nt * 8 + tig * 2;
            *(float2*)&zbuf[gid * ZSTR + col] = make_float2(cc[nt][0], cc[nt][1]);
            *(float2*)&zbuf[(gid + 8) * ZSTR + col] = make_float2(cc[nt][2], cc[nt][3]);
        }
        __syncthreads();

        // state phase: owned rows
        #pragma unroll
        for (int q = 0; q < 4; q++) {
            int r = r0 + q;
            float zi = zbuf[r * ZSTR + lane];
            float zf = zbuf[r * ZSTR + 32 + lane];
            float zg = zbuf[r * ZSTR + 64 + lane];
            float zo = zbuf[r * ZSTR + 96 + lane];
            float ig = sigmf(zi);
            float fg = sigmf(zf);
            float gg = tanhf_(zg);
            float og = sigmf(zo);
            cst[q] = fg * cst[q] + ig * gg;
            h[q] = og * tanhf_(cst[q]);
            u32 hib = tf32_of(h[q]);
            float hif = __uint_as_float(hib);
            sAhi[r * ASTR + 32 + lane] = hif;
            sAlo[r * ASTR + 32 + lane] = h[q] - hif;
            if (t + 1 < Tc) {
                float hc = hcn[q];
                u32 cb2 = tf32_of(hc);
                float cf2 = __uint_as_float(cb2);
                sAhi[r * ASTR + lane] = cf2;
                sAlo[r * ASTR + lane] = hc - cf2;
            }
        }
        __syncthreads();
    }

    // head: y = silu(h @ hw1 + hb1) @ hw2 + hb2   (warp owns rows r0..r0+4)
    #pragma unroll
    for (int q = 0; q < 4; q++) {
        int row = rb + r0 + q;
        int b = row / Nc;
        int n = row % Nc;
        float a = hb1S[lane];
        #pragma unroll 8
        for (int i = 0; i < 32; i++) {
            float hi = __shfl_sync(FULLMASK, h[q], i);
            a += hi * hw1S[i * 32 + lane];
        }
        float y1 = siluf(a);
        float o = (lane < PREDc) ? hb2S[lane] : 0.f;
        #pragma unroll 8
        for (int j = 0; j < 32; j++) {
            float yj = __shfl_sync(FULLMASK, y1, j);
            if (lane < PREDc) o += yj * hw2S[j * PREDc + lane];
        }
        if (lane < Pout) out[((size_t)b * Pout + lane) * Nc + n] = o;
    }
}

// ---------------- launch ----------------
extern "C" void kernel_launch(void* const* d_in, const int* in_sizes, int n_in,
                              void* d_out, int out_size) {
    const float* x       = (const float*)d_in[0];
    const float* xraw    = (const float*)d_in[1];
    const float* W       = (const float*)d_in[3];
    const int*   members = (const int*)d_in[4];
    const int*   centers = (const int*)d_in[5];
    const int*   offsets = (const int*)d_in[6];
    const float* ipw     = (const float*)d_in[7];
    const float* ipb     = (const float*)d_in[8];
    const float* cw      = (const float*)d_in[9];
    const float* cb      = (const float*)d_in[10];
    const float* wx      = (const float*)d_in[11];
    const float* wh      = (const float*)d_in[12];
    const float* lb      = (const float*)d_in[13];
    const float* hw1     = (const float*)d_in[14];
    const float* hb1     = (const float*)d_in[15];
    const float* hw2     = (const float*)d_in[16];
    const float* hb2     = (const float*)d_in[17];
    float* out = (float*)d_out;
    int Pout = out_size / (Bc * Nc);

    int smem_slice = ((Nc + 1) * 16 + 256 + 16) * sizeof(float);                       // 65152
    int smem_lstm  = (16 * ASTR * 2 + 16 * ZSTR + 128 + 1024 + 32 + 384 + 16) * 4;     // ~23.5KB
    cudaFuncSetAttribute(k_slice2, cudaFuncAttributeMaxDynamicSharedMemorySize, smem_slice);
    cudaFuncSetAttribute(k_lstm_tc, cudaFuncAttributeMaxDynamicSharedMemorySize, smem_lstm);

    k_feat_zero<<<254, 256>>>(xraw);                       // feat + zero degs + minmax init
    k_sim_build<<<1004, 256>>>(members, centers, offsets); // sim + atomic minmax + edge build
    k_sort_nodes<<<4, 256>>>();
    k_wdf2<<<65, 256>>>(W, ipw, ipb, cw);
    k_slice2<<<Bc * Tc * 2, 512, smem_slice>>>(x, cb);
    k_lstm_tc<<<Bc * Nc / 16, 128, smem_lstm>>>(wx, wh, lb, hw1, hb1, hw2, hb2, out, Pout);
}

// round 16
// speedup vs baseline: 1.1257x; 1.0174x over previous
#include <cuda_runtime.h>
#include <math.h>

#define FULLMASK 0xffffffffu

#define Bc 8
#define Tc 24
#define Nc 1000
#define Ec 1000
#define F_INc 16
#define C_RAWc 8
#define DMc 32
#define HCc 32
#define PREDc 12
#define LAMc 0.3f
#define EPSc 1e-8f
#define MAXD 64
#define ESTRIDE 24     // padded edge member list stride (int4-aligned)

typedef unsigned long long u64;
typedef unsigned int u32;

// ---------------- scratch (device globals; no allocation) ----------------
__device__ int   g_edge_nodes[Ec * ESTRIDE];
__device__ int   g_edge_cnt[Ec];
__device__ int   g_node_edges[Nc * MAXD];
__device__ int   g_node_deg[Nc];
__device__ float g_feat[Bc * Nc * 16];
__device__ float g_msum[Bc * Ec];
__device__ u32   g_mnU[Bc];
__device__ u32   g_mxU[Bc];
__device__ float g_Wd[Bc * Ec];         // Wd/De (pre-scaled by edge count)
__device__ float g_dvi[Bc * Nc];
__device__ float g_ipwc[F_INc * DMc];   // folded ipw @ cw
__device__ float g_ipbc[DMc];           // folded ipb @ cw
__device__ float g_hc[(size_t)Bc * Nc * Tc * HCc];   // conv outputs (LSTM inputs)

// ---------------- math helpers ----------------
__device__ __forceinline__ float sigmf(float x) { return __fdividef(1.f, 1.f + __expf(-x)); }
__device__ __forceinline__ float tanha(float x) {
    float r; asm("tanh.approx.f32 %0, %1;" : "=f"(r) : "f"(x)); return r;
}
__device__ __forceinline__ float sigm_t(float x) { return fmaf(0.5f, tanha(0.5f * x), 0.5f); }
__device__ __forceinline__ float silu_t(float x) { return x * sigm_t(x); }

__device__ __forceinline__ u32 tf32_of(float f) {
    u32 r; asm("cvt.rna.tf32.f32 %0, %1;" : "=r"(r) : "f"(f)); return r;
}
__device__ __forceinline__ void mma_tf32(float c[4], u32 a0, u32 a1, u32 a2, u32 a3,
                                         u32 b0, u32 b1) {
    asm volatile(
        "mma.sync.aligned.m16n8k8.row.col.f32.tf32.tf32.f32 "
        "{%0,%1,%2,%3}, {%4,%5,%6,%7}, {%8,%9}, {%0,%1,%2,%3};"
        : "+f"(c[0]), "+f"(c[1]), "+f"(c[2]), "+f"(c[3])
        : "r"(a0), "r"(a1), "r"(a2), "r"(a3), "r"(b0), "r"(b1));
}

// ---------------- K1: dynamic features (blocks 0..249) + zero degs / minmax init (250..253) ----------------
__global__ void k_feat_zero(const float* __restrict__ xraw) {
    if (blockIdx.x >= 250) {
        int i = (blockIdx.x - 250) * blockDim.x + threadIdx.x;
        if (i < Nc) g_node_deg[i] = 0;
        if (blockIdx.x == 250 && threadIdx.x < Bc) {
            g_mnU[threadIdx.x] = 0x7F800000u;  // +inf (nonneg-float uint ordering)
            g_mxU[threadIdx.x] = 0u;
        }
        return;
    }
    int idx = blockIdx.x * blockDim.x + threadIdx.x;
    if (idx >= Bc * Nc * C_RAWc) return;
    int c = idx % C_RAWc;
    int n = (idx / C_RAWc) % Nc;
    int b = idx / (C_RAWc * Nc);
    float s1 = 0.f, s2 = 0.f;
    #pragma unroll
    for (int t = 0; t < Tc; t++) {
        float v = xraw[((b * Tc + t) * Nc + n) * C_RAWc + c];
        s1 += v; s2 += v * v;
    }
    float mean = s1 * (1.f / Tc);
    float var = s2 * (1.f / Tc) - mean * mean;
    if (var < 0.f) var = 0.f;
    g_feat[(b * Nc + n) * 16 + c] = mean;
    g_feat[(b * Nc + n) * 16 + C_RAWc + c] = sqrtf(var);
}

// ---------------- K2: per-edge similarity + batch min/max (0..999); edge-list build (1000..1003) ----------------
__global__ void k_sim_build(const int* __restrict__ members,
                            const int* __restrict__ centers,
                            const int* __restrict__ offsets) {
    if (blockIdx.x >= 1000) {
        int e = (blockIdx.x - 1000) * blockDim.x + threadIdx.x;
        if (e >= Ec) return;
        int s = offsets[e], t = offsets[e + 1];
        int list[ESTRIDE];
        int cnt = 0;
        for (int m = s; m < t && cnt < ESTRIDE; m++) {
            int n = members[m];
            bool dup = false;
            for (int k = 0; k < cnt; k++) if (list[k] == n) { dup = true; break; }
            if (!dup) list[cnt++] = n;
        }
        {
            int c = centers[e];
            bool dup = false;
            for (int k = 0; k < cnt; k++) if (list[k] == c) { dup = true; break; }
            if (!dup && cnt < ESTRIDE) list[cnt++] = c;
        }
        g_edge_cnt[e] = cnt;
        for (int k = 0; k < cnt; k++) {
            int n = list[k];
            g_edge_nodes[e * ESTRIDE + k] = n;
            int pos = atomicAdd(&g_node_deg[n], 1);
            if (pos < MAXD) g_node_edges[n * MAXD + pos] = e;
        }
        for (int k = cnt; k < ESTRIDE; k++) g_edge_nodes[e * ESTRIDE + k] = Nc;
        return;
    }
    int gid = blockIdx.x * (blockDim.x >> 5) + (threadIdx.x >> 5);
    if (gid >= Bc * Ec) return;
    int e = gid % Ec;
    int b = gid / Ec;
    int lane = threadIdx.x & 31;
    int s = offsets[e];
    int cntm = offsets[e + 1] - s;
    int cn = centers[e];
    const float4* cf4 = (const float4*)(g_feat + (b * Nc + cn) * 16);
    float4 c0 = cf4[0], c1 = cf4[1], c2 = cf4[2], c3 = cf4[3];
    float cn2 = c0.x*c0.x + c0.y*c0.y + c0.z*c0.z + c0.w*c0.w
              + c1.x*c1.x + c1.y*c1.y + c1.z*c1.z + c1.w*c1.w
              + c2.x*c2.x + c2.y*c2.y + c2.z*c2.z + c2.w*c2.w
              + c3.x*c3.x + c3.y*c3.y + c3.z*c3.z + c3.w*c3.w;
    float cnorm = sqrtf(cn2);
    float acc = 0.f;
    for (int m = lane; m < cntm; m += 32) {
        int n = members[s + m];
        const float4* mf4 = (const float4*)(g_feat + (b * Nc + n) * 16);
        float4 m0 = mf4[0], m1 = mf4[1], m2 = mf4[2], m3 = mf4[3];
        float dot = m0.x*c0.x + m0.y*c0.y + m0.z*c0.z + m0.w*c0.w
                  + m1.x*c1.x + m1.y*c1.y + m1.z*c1.z + m1.w*c1.w
                  + m2.x*c2.x + m2.y*c2.y + m2.z*c2.z + m2.w*c2.w
                  + m3.x*c3.x + m3.y*c3.y + m3.z*c3.z + m3.w*c3.w;
        float mn2 = m0.x*m0.x + m0.y*m0.y + m0.z*m0.z + m0.w*m0.w
                  + m1.x*m1.x + m1.y*m1.y + m1.z*m1.z + m1.w*m1.w
                  + m2.x*m2.x + m2.y*m2.y + m2.z*m2.z + m2.w*m2.w
                  + m3.x*m3.x + m3.y*m3.y + m3.z*m3.z + m3.w*m3.w;
        float sim = dot / (sqrtf(mn2) * cnorm + EPSc);
        acc += fminf(fmaxf(sim, 0.f), 1.f);
    }
    #pragma unroll
    for (int o = 16; o > 0; o >>= 1) acc += __shfl_xor_sync(FULLMASK, acc, o);
    if (lane == 0) {
        float count = (float)cntm;
        if (count < 1.f) count = 1.f;
        float v = acc / count;
        g_msum[b * Ec + e] = v;
        u32 vb = __float_as_uint(v);
        atomicMin(&g_mnU[b], vb);
        atomicMax(&g_mxU[b], vb);
    }
}

// ---------------- sort node edge lists (deterministic gather order) ----------------
__global__ void k_sort_nodes() {
    int n = blockIdx.x * blockDim.x + threadIdx.x;
    if (n >= Nc) return;
    int d = g_node_deg[n];
    if (d > MAXD) d = MAXD;
    g_node_deg[n] = d;
    int* L = g_node_edges + n * MAXD;
    for (int i = 1; i < d; i++) {
        int key = L[i];
        int j = i - 1;
        while (j >= 0 && L[j] > key) { L[j + 1] = L[j]; j--; }
        L[j + 1] = key;
    }
    int d8 = (d + 7) & ~7;
    if (d8 > MAXD) d8 = MAXD;
    for (int i = d; i < d8; i++) L[i] = Ec;  // dummy: smem row 1000 zeroed
}

// ---------------- Wd + dvi, 64 parallel (b, slice) blocks; block 64 = conv fold ----------------
__global__ __launch_bounds__(256) void k_wdf2(const float* __restrict__ W,
                                              const float* __restrict__ ipw,
                                              const float* __restrict__ ipb,
                                              const float* __restrict__ cw) {
    int blk = blockIdx.x;
    int tid = threadIdx.x;
    if (blk < 64) {
        __shared__ float sWd[Ec];
        int b = blk >> 3, part = blk & 7;
        float mn = __uint_as_float(g_mnU[b]);
        float mx = __uint_as_float(g_mxU[b]);
        float inv = __fdividef(1.f, mx - mn + EPSc);
        for (int e = tid; e < Ec; e += 256) {
            float v = (g_msum[b * Ec + e] - mn) * inv;
            sWd[e] = W[e] * (1.f + LAMc * v);
        }
        __syncthreads();
        int s0 = part * 125;
        for (int e = s0 + tid; e < s0 + 125; e += 256)
            g_Wd[b * Ec + e] = __fdividef(sWd[e], (float)g_edge_cnt[e]);  // pre-scale by De
        for (int n = s0 + tid; n < s0 + 125; n += 256) {
            int d = g_node_deg[n];
            const int* L = g_node_edges + n * MAXD;
            float s = 0.f;
            for (int i = 0; i < d; i++) s += sWd[L[i]];
            g_dvi[b * Nc + n] = rsqrtf(fmaxf(s, EPSc));
        }
    } else {
        for (int it = tid; it < F_INc * DMc; it += 256) {
            int k = it >> 5, j = it & 31;
            float s = 0.f;
            #pragma unroll
            for (int f = 0; f < DMc; f++) s += ipw[k * DMc + f] * cw[f * HCc + j];
            g_ipwc[it] = s;
        }
        if (tid < 32) {
            float sb = 0.f;
            #pragma unroll
            for (int f = 0; f < DMc; f++) sb += ipb[f] * cw[f * HCc + tid];
            g_ipbc[tid] = sb;
        }
    }
}

// ---------------- half-slice kernel: block per ((b,t), feature-half) ----------------
__global__ __launch_bounds__(512) void k_slice2(const float* __restrict__ x,
                                                const float* __restrict__ cbg) {
    extern __shared__ float xs[];          // (Nc+1)*16, reused for edge features
    float* sipw = xs + (Nc + 1) * 16;      // 256: [k*16 + j]
    float* sipb = sipw + 256;              // 16
    int blk = blockIdx.x;
    int bt = blk >> 1;
    int half = blk & 1;
    int b = bt / Tc;
    int t = bt % Tc;
    int tid = threadIdx.x;
    int lane = tid & 31, w = tid >> 5;
    int fl = lane & 15;
    int sel = lane >> 4;
    int h16 = half * 16;

    if (tid < 256) {
        int k = tid >> 4, j = tid & 15;
        sipw[tid] = g_ipwc[k * 32 + h16 + j];
    }
    if (tid < 16) sipb[tid] = g_ipbc[h16 + tid];
    __syncthreads();

    const float* xb = x + (size_t)bt * Nc * F_INc;
    for (int i = tid; i < (Nc + 1) * 4; i += 512) {
        int n = i >> 2, q = (i & 3) * 4;
        float a0 = 0.f, a1 = 0.f, a2 = 0.f, a3 = 0.f;
        if (n < Nc) {
            const float* xr = xb + n * F_INc;
            a0 = sipb[q]; a1 = sipb[q + 1]; a2 = sipb[q + 2]; a3 = sipb[q + 3];
            #pragma unroll
            for (int k = 0; k < F_INc; k++) {
                float xv = xr[k];
                a0 += xv * sipw[k * 16 + q];
                a1 += xv * sipw[k * 16 + q + 1];
                a2 += xv * sipw[k * 16 + q + 2];
                a3 += xv * sipw[k * 16 + q + 3];
            }
            float d = g_dvi[b * Nc + n];
            a0 *= d; a1 *= d; a2 *= d; a3 *= d;
        }
        *(float4*)(xs + n * 16 + q) = make_float4(a0, a1, a2, a3);
    }
    __syncthreads();

    int e_base = w * 64;
    float u_reg[32];
    #pragma unroll
    for (int s = 0; s < 32; s++) {
        int e = e_base + 2 * s + sel;
        float uv = 0.f;
        if (e < Ec) {
            const int4* ip = (const int4*)(g_edge_nodes + e * ESTRIDE);
            int4 a0 = ip[0], a1 = ip[1], a2 = ip[2], a3 = ip[3], a4 = ip[4], a5 = ip[5];
            float p0 = xs[a0.x * 16 + fl] + xs[a1.x * 16 + fl]
                     + xs[a2.x * 16 + fl] + xs[a3.x * 16 + fl]
                     + xs[a4.x * 16 + fl] + xs[a5.x * 16 + fl];
            float p1 = xs[a0.y * 16 + fl] + xs[a1.y * 16 + fl]
                     + xs[a2.y * 16 + fl] + xs[a3.y * 16 + fl]
                     + xs[a4.y * 16 + fl] + xs[a5.y * 16 + fl];
            float p2 = xs[a0.z * 16 + fl] + xs[a1.z * 16 + fl]
                     + xs[a2.z * 16 + fl] + xs[a3.z * 16 + fl]
                     + xs[a4.z * 16 + fl] + xs[a5.z * 16 + fl];
            float p3 = xs[a0.w * 16 + fl] + xs[a1.w * 16 + fl]
                     + xs[a2.w * 16 + fl] + xs[a3.w * 16 + fl]
                     + xs[a4.w * 16 + fl] + xs[a5.w * 16 + fl];
            uv = ((p0 + p1) + (p2 + p3)) * g_Wd[b * Ec + e];
        }
        u_reg[s] = uv;
    }
    __syncthreads();

    #pragma unroll
    for (int s = 0; s < 32; s++) {
        int e = e_base + 2 * s + sel;
        if (e < Ec) xs[e * 16 + fl] = u_reg[s];
    }
    if (tid < 16) xs[Nc * 16 + tid] = 0.f;
    __syncthreads();

    float cbv = cbg[h16 + fl];
    for (int np = w; np < Nc / 2; np += 16) {
        int n = np * 2 + sel;
        int deg = g_node_deg[n];
        int d8 = (deg + 7) & ~7;
        const int* L = g_node_edges + n * MAXD;
        float p0 = 0.f, p1 = 0.f;
        for (int k = 0; k < d8; k += 8) {
            int4 a = *(const int4*)(L + k);
            int4 b2 = *(const int4*)(L + k + 4);
            p0 += xs[a.x * 16 + fl] + xs[a.z * 16 + fl]
                + xs[b2.x * 16 + fl] + xs[b2.z * 16 + fl];
            p1 += xs[a.y * 16 + fl] + xs[a.w * 16 + fl]
                + xs[b2.y * 16 + fl] + xs[b2.w * 16 + fl];
        }
        float z = (p0 + p1) * g_dvi[b * Nc + n] + cbv;
        g_hc[((size_t)(b * Nc + n) * Tc + t) * 32 + h16 + fl] = silu_t(z);
    }
}

// ---------------- LSTM: tensor-core recurrence (tf32 2-pass split), 16 rows/block ----------------
#define ASTR 68
#define ZSTR 132
__global__ __launch_bounds__(128) void k_lstm_tc(
    const float* __restrict__ wx, const float* __restrict__ wh,
    const float* __restrict__ lb,
    const float* __restrict__ hw1, const float* __restrict__ hb1,
    const float* __restrict__ hw2, const float* __restrict__ hb2,
    float* __restrict__ out, int Pout) {
    extern __shared__ __align__(16) float sm[];
    float* sAhi = sm;                    // 16*68 = 1088
    float* sAlo = sAhi + 16 * ASTR;      // 1088
    float* zbuf = sAlo + 16 * ASTR;      // 16*132 = 2112
    float* lbS  = zbuf + 16 * ZSTR;      // 128
    float* hw1S = lbS + 128;             // 1024
    float* hb1S = hw1S + 1024;           // 32
    float* hw2S = hb1S + 32;             // 384
    float* hb2S = hw2S + 384;            // 16

    int tid = threadIdx.x;
    int lane = tid & 31, w = tid >> 5;
    int gid = lane >> 2, tig = lane & 3;
    int gblk = w;
    int rb = blockIdx.x * 16;

    for (int i = tid; i < 1024; i += 128) hw1S[i] = hw1[i];
    for (int i = tid; i < 384; i += 128) hw2S[i] = hw2[i];
    if (tid < 128) lbS[tid] = lb[tid];
    if (tid < 32) hb1S[tid] = hb1[tid];
    if (tid < PREDc) hb2S[tid] = hb2[tid];

    u32 bw0[8][4], bw1[8][4];
    #pragma unroll
    for (int ks = 0; ks < 8; ks++) {
        #pragma unroll
        for (int nt = 0; nt < 4; nt++) {
            int col = gblk * 32 + nt * 8 + gid;
            int k0 = ks * 8 + tig;
            int k1 = k0 + 4;
            float f0 = (k0 < 32) ? wx[k0 * 128 + col] : wh[(k0 - 32) * 128 + col];
            float f1 = (k1 < 32) ? wx[k1 * 128 + col] : wh[(k1 - 32) * 128 + col];
            bw0[ks][nt] = tf32_of(f0);
            bw1[ks][nt] = tf32_of(f1);
        }
    }

    int r0 = w * 4;
    float h[4], cst[4];
    #pragma unroll
    for (int q = 0; q < 4; q++) {
        h[q] = 0.f; cst[q] = 0.f;
        int r = r0 + q;
        float hc = g_hc[((size_t)(rb + r) * Tc) * 32 + lane];
        u32 hib = tf32_of(hc);
        float hif = __uint_as_float(hib);
        sAhi[r * ASTR + lane] = hif;
        sAlo[r * ASTR + lane] = hc - hif;
        sAhi[r * ASTR + 32 + lane] = 0.f;
        sAlo[r * ASTR + 32 + lane] = 0.f;
    }
    __syncthreads();

    for (int t = 0; t < Tc; t++) {
        float hcn[4];
        if (t + 1 < Tc) {
            #pragma unroll
            for (int q = 0; q < 4; q++)
                hcn[q] = g_hc[((size_t)(rb + r0 + q) * Tc + t + 1) * 32 + lane];
        }

        float cc[4][4];
        #pragma unroll
        for (int nt = 0; nt < 4; nt++) {
            int col = gblk * 32 + nt * 8 + tig * 2;
            cc[nt][0] = lbS[col];
            cc[nt][1] = lbS[col + 1];
            cc[nt][2] = lbS[col];
            cc[nt][3] = lbS[col + 1];
        }
        #pragma unroll
        for (int ks = 0; ks < 8; ks++) {
            int ca = ks * 8 + tig;
            u32 a0h = __float_as_uint(sAhi[gid * ASTR + ca]);
            u32 a1h = __float_as_uint(sAhi[(gid + 8) * ASTR + ca]);
            u32 a2h = __float_as_uint(sAhi[gid * ASTR + ca + 4]);
            u32 a3h = __float_as_uint(sAhi[(gid + 8) * ASTR + ca + 4]);
            u32 a0l = __float_as_uint(sAlo[gid * ASTR + ca]);
            u32 a1l = __float_as_uint(sAlo[(gid + 8) * ASTR + ca]);
            u32 a2l = __float_as_uint(sAlo[gid * ASTR + ca + 4]);
            u32 a3l = __float_as_uint(sAlo[(gid + 8) * ASTR + ca + 4]);
            #pragma unroll
            for (int nt = 0; nt < 4; nt++) {
                mma_tf32(cc[nt], a0h, a1h, a2h, a3h, bw0[ks][nt], bw1[ks][nt]);
                mma_tf32(cc[nt], a0l, a1l, a2l, a3l, bw0[ks][nt], bw1[ks][nt]);
            }
        }
        #pragma unroll
        for (int nt = 0; nt < 4; nt++) {
            int col = gblk * 32 + nt * 8 + tig * 2;
            *(float2*)&zbuf[gid * ZSTR + col] = make_float2(cc[nt][0], cc[nt][1]);
            *(float2*)&zbuf[(gid + 8) * ZSTR + col] = make_float2(cc[nt][2], cc[nt][3]);
        }
        __syncthreads();

        #pragma unroll
        for (int q = 0; q < 4; q++) {
            int r = r0 + q;
            float zi = zbuf[r * ZSTR + lane];
            float zf = zbuf[r * ZSTR + 32 + lane];
            float zg = zbuf[r * ZSTR + 64 + lane];
            float zo = zbuf[r * ZSTR + 96 + lane];
            float ig = sigm_t(zi);
            float fg = sigm_t(zf);
            float gg = tanha(zg);
            float og = sigm_t(zo);
            cst[q] = fg * cst[q] + ig * gg;
            h[q] = og * tanha(cst[q]);
            u32 hib = tf32_of(h[q]);
            float hif = __uint_as_float(hib);
            sAhi[r * ASTR + 32 + lane] = hif;
            sAlo[r * ASTR + 32 + lane] = h[q] - hif;
            if (t + 1 < Tc) {
                float hc = hcn[q];
                u32 cb2 = tf32_of(hc);
                float cf2 = __uint_as_float(cb2);
                sAhi[r * ASTR + lane] = cf2;
                sAlo[r * ASTR + lane] = hc - cf2;
            }
        }
        __syncthreads();
    }

    // head: y = silu(h @ hw1 + hb1) @ hw2 + hb2   (warp owns rows r0..r0+4)
    #pragma unroll
    for (int q = 0; q < 4; q++) {
        int row = rb + r0 + q;
        int b = row / Nc;
        int n = row % Nc;
        float a = hb1S[lane];
        #pragma unroll 8
        for (int i = 0; i < 32; i++) {
            float hi = __shfl_sync(FULLMASK, h[q], i);
            a += hi * hw1S[i * 32 + lane];
        }
        float y1 = silu_t(a);
        float o = (lane < PREDc) ? hb2S[lane] : 0.f;
        #pragma unroll 8
        for (int j = 0; j < 32; j++) {
            float yj = __shfl_sync(FULLMASK, y1, j);
            if (lane < PREDc) o += yj * hw2S[j * PREDc + lane];
        }
        if (lane < Pout) out[((size_t)b * Pout + lane) * Nc + n] = o;
    }
}

// ---------------- launch ----------------
extern "C" void kernel_launch(void* const* d_in, const int* in_sizes, int n_in,
                              void* d_out, int out_size) {
    const float* x       = (const float*)d_in[0];
    const float* xraw    = (const float*)d_in[1];
    const float* W       = (const float*)d_in[3];
    const int*   members = (const int*)d_in[4];
    const int*   centers = (const int*)d_in[5];
    const int*   offsets = (const int*)d_in[6];
    const float* ipw     = (const float*)d_in[7];
    const float* ipb     = (const float*)d_in[8];
    const float* cw      = (const float*)d_in[9];
    const float* cb      = (const float*)d_in[10];
    const float* wx      = (const float*)d_in[11];
    const float* wh      = (const float*)d_in[12];
    const float* lb      = (const float*)d_in[13];
    const float* hw1     = (const float*)d_in[14];
    const float* hb1     = (const float*)d_in[15];
    const float* hw2     = (const float*)d_in[16];
    const float* hb2     = (const float*)d_in[17];
    float* out = (float*)d_out;
    int Pout = out_size / (Bc * Nc);

    int smem_slice = ((Nc + 1) * 16 + 256 + 16) * sizeof(float);                       // 65152
    int smem_lstm  = (16 * ASTR * 2 + 16 * ZSTR + 128 + 1024 + 32 + 384 + 16) * 4;     // ~23.5KB
    cudaFuncSetAttribute(k_slice2, cudaFuncAttributeMaxDynamicSharedMemorySize, smem_slice);
    cudaFuncSetAttribute(k_lstm_tc, cudaFuncAttributeMaxDynamicSharedMemorySize, smem_lstm);

    k_feat_zero<<<254, 256>>>(xraw);                       // feat + zero degs + minmax init
    k_sim_build<<<1004, 256>>>(members, centers, offsets); // sim + atomic minmax + edge build
    k_sort_nodes<<<4, 256>>>();
    k_wdf2<<<65, 256>>>(W, ipw, ipb, cw);
    k_slice2<<<Bc * Tc * 2, 512, smem_slice>>>(x, cb);
    k_lstm_tc<<<Bc * Nc / 16, 128, smem_lstm>>>(wx, wh, lb, hw1, hb1, hw2, hb2, out, Pout);
}

// round 17
// speedup vs baseline: 1.2259x; 1.0890x over previous
#include <cuda_runtime.h>
#include <math.h>

#define FULLMASK 0xffffffffu

#define Bc 8
#define Tc 24
#define Nc 1000
#define Ec 1000
#define F_INc 16
#define C_RAWc 8
#define DMc 32
#define HCc 32
#define PREDc 12
#define LAMc 0.3f
#define EPSc 1e-8f
#define MAXD 64
#define ESTRIDE 24     // padded edge member list stride (int4-aligned)

typedef unsigned long long u64;
typedef unsigned int u32;

// ---------------- scratch (device globals; no allocation) ----------------
__device__ int   g_edge_nodes[Ec * ESTRIDE];
__device__ int   g_edge_cnt[Ec];
__device__ int   g_node_edges[Nc * MAXD];
__device__ int   g_node_deg[Nc];        // BSS-zero at load; re-zeroed by lstm tail each run
__device__ float g_feat[Bc * Nc * 16];
__device__ float g_msum[Bc * Ec];
__device__ u32   g_mnU[Bc];
__device__ u32   g_mxU[Bc];
__device__ float g_Wd[Bc * Ec];         // Wd/De (pre-scaled by edge count)
__device__ float g_dvi[Bc * Nc];
__device__ float g_T[Bc * Nc];          // (A @ 1)_n : bias-path gather, t-independent
__device__ float g_ipwc[F_INc * DMc];   // folded ipw @ cw
__device__ float g_ipbc[DMc];           // folded ipb @ cw
__device__ float g_hc[(size_t)Bc * Nc * Tc * HCc];   // conv outputs (LSTM inputs)

// ---------------- math helpers ----------------
__device__ __forceinline__ float tanha(float x) {
    float r; asm("tanh.approx.f32 %0, %1;" : "=f"(r) : "f"(x)); return r;
}
__device__ __forceinline__ float sigm_t(float x) { return fmaf(0.5f, tanha(0.5f * x), 0.5f); }
__device__ __forceinline__ float silu_t(float x) { return x * sigm_t(x); }

__device__ __forceinline__ u32 tf32_of(float f) {
    u32 r; asm("cvt.rna.tf32.f32 %0, %1;" : "=r"(r) : "f"(f)); return r;
}
__device__ __forceinline__ void mma_tf32(float c[4], u32 a0, u32 a1, u32 a2, u32 a3,
                                         u32 b0, u32 b1) {
    asm volatile(
        "mma.sync.aligned.m16n8k8.row.col.f32.tf32.tf32.f32 "
        "{%0,%1,%2,%3}, {%4,%5,%6,%7}, {%8,%9}, {%0,%1,%2,%3};"
        : "+f"(c[0]), "+f"(c[1]), "+f"(c[2]), "+f"(c[3])
        : "r"(a0), "r"(a1), "r"(a2), "r"(a3), "r"(b0), "r"(b1));
}

// ---------------- K1: dynamic features (0..249) + edge-list build (250..253) + minmax init ----------------
// node degs are zero at entry: BSS on first run, lstm tail re-zeroes for replays.
__global__ void k_feat_build(const float* __restrict__ xraw,
                             const int* __restrict__ members,
                             const int* __restrict__ centers,
                             const int* __restrict__ offsets) {
    if (blockIdx.x >= 250) {
        if (blockIdx.x == 250 && threadIdx.x < Bc) {
            g_mnU[threadIdx.x] = 0x7F800000u;  // +inf (nonneg-float uint ordering)
            g_mxU[threadIdx.x] = 0u;
        }
        int e = (blockIdx.x - 250) * blockDim.x + threadIdx.x;
        if (e >= Ec) return;
        int s = offsets[e], t = offsets[e + 1];
        int list[ESTRIDE];
        int cnt = 0;
        for (int m = s; m < t && cnt < ESTRIDE; m++) {
            int n = members[m];
            bool dup = false;
            for (int k = 0; k < cnt; k++) if (list[k] == n) { dup = true; break; }
            if (!dup) list[cnt++] = n;
        }
        {
            int c = centers[e];
            bool dup = false;
            for (int k = 0; k < cnt; k++) if (list[k] == c) { dup = true; break; }
            if (!dup && cnt < ESTRIDE) list[cnt++] = c;
        }
        g_edge_cnt[e] = cnt;
        for (int k = 0; k < cnt; k++) {
            int n = list[k];
            g_edge_nodes[e * ESTRIDE + k] = n;
            int pos = atomicAdd(&g_node_deg[n], 1);
            if (pos < MAXD) g_node_edges[n * MAXD + pos] = e;
        }
        for (int k = cnt; k < ESTRIDE; k++) g_edge_nodes[e * ESTRIDE + k] = Nc;
        return;
    }
    int idx = blockIdx.x * blockDim.x + threadIdx.x;
    if (idx >= Bc * Nc * C_RAWc) return;
    int c = idx % C_RAWc;
    int n = (idx / C_RAWc) % Nc;
    int b = idx / (C_RAWc * Nc);
    float s1 = 0.f, s2 = 0.f;
    #pragma unroll
    for (int t = 0; t < Tc; t++) {
        float v = xraw[((b * Tc + t) * Nc + n) * C_RAWc + c];
        s1 += v; s2 += v * v;
    }
    float mean = s1 * (1.f / Tc);
    float var = s2 * (1.f / Tc) - mean * mean;
    if (var < 0.f) var = 0.f;
    g_feat[(b * Nc + n) * 16 + c] = mean;
    g_feat[(b * Nc + n) * 16 + C_RAWc + c] = sqrtf(var);
}

// ---------------- K2: per-edge similarity + batch min/max (0..999); node-list sort (1000..1003) ----------------
__global__ void k_sim_sort(const int* __restrict__ members,
                           const int* __restrict__ centers,
                           const int* __restrict__ offsets) {
    if (blockIdx.x >= 1000) {
        int n = (blockIdx.x - 1000) * blockDim.x + threadIdx.x;
        if (n >= Nc) return;
        int d = g_node_deg[n];
        if (d > MAXD) d = MAXD;
        g_node_deg[n] = d;
        int* L = g_node_edges + n * MAXD;
        for (int i = 1; i < d; i++) {
            int key = L[i];
            int j = i - 1;
            while (j >= 0 && L[j] > key) { L[j + 1] = L[j]; j--; }
            L[j + 1] = key;
        }
        int d8 = (d + 7) & ~7;
        if (d8 > MAXD) d8 = MAXD;
        for (int i = d; i < d8; i++) L[i] = Ec;  // dummy: sSDW[Ec]=0, xs row 1000 zeroed
        return;
    }
    int gid = blockIdx.x * (blockDim.x >> 5) + (threadIdx.x >> 5);
    if (gid >= Bc * Ec) return;
    int e = gid % Ec;
    int b = gid / Ec;
    int lane = threadIdx.x & 31;
    int s = offsets[e];
    int cntm = offsets[e + 1] - s;
    int cn = centers[e];
    const float4* cf4 = (const float4*)(g_feat + (b * Nc + cn) * 16);
    float4 c0 = cf4[0], c1 = cf4[1], c2 = cf4[2], c3 = cf4[3];
    float cn2 = c0.x*c0.x + c0.y*c0.y + c0.z*c0.z + c0.w*c0.w
              + c1.x*c1.x + c1.y*c1.y + c1.z*c1.z + c1.w*c1.w
              + c2.x*c2.x + c2.y*c2.y + c2.z*c2.z + c2.w*c2.w
              + c3.x*c3.x + c3.y*c3.y + c3.z*c3.z + c3.w*c3.w;
    float cnorm = sqrtf(cn2);
    float acc = 0.f;
    for (int m = lane; m < cntm; m += 32) {
        int n = members[s + m];
        const float4* mf4 = (const float4*)(g_feat + (b * Nc + n) * 16);
        float4 m0 = mf4[0], m1 = mf4[1], m2 = mf4[2], m3 = mf4[3];
        float dot = m0.x*c0.x + m0.y*c0.y + m0.z*c0.z + m0.w*c0.w
                  + m1.x*c1.x + m1.y*c1.y + m1.z*c1.z + m1.w*c1.w
                  + m2.x*c2.x + m2.y*c2.y + m2.z*c2.z + m2.w*c2.w
                  + m3.x*c3.x + m3.y*c3.y + m3.z*c3.z + m3.w*c3.w;
        float mn2 = m0.x*m0.x + m0.y*m0.y + m0.z*m0.z + m0.w*m0.w
                  + m1.x*m1.x + m1.y*m1.y + m1.z*m1.z + m1.w*m1.w
                  + m2.x*m2.x + m2.y*m2.y + m2.z*m2.z + m2.w*m2.w
                  + m3.x*m3.x + m3.y*m3.y + m3.z*m3.z + m3.w*m3.w;
        float sim = dot / (sqrtf(mn2) * cnorm + EPSc);
        acc += fminf(fmaxf(sim, 0.f), 1.f);
    }
    #pragma unroll
    for (int o = 16; o > 0; o >>= 1) acc += __shfl_xor_sync(FULLMASK, acc, o);
    if (lane == 0) {
        float count = (float)cntm;
        if (count < 1.f) count = 1.f;
        float v = acc / count;
        g_msum[b * Ec + e] = v;
        u32 vb = __float_as_uint(v);
        atomicMin(&g_mnU[b], vb);
        atomicMax(&g_mxU[b], vb);
    }
}

// ---------------- Wd + dvi, 64 parallel (b, slice) blocks; block 64 = conv fold ----------------
__global__ __launch_bounds__(256) void k_wdf2(const float* __restrict__ W,
                                              const float* __restrict__ ipw,
                                              const float* __restrict__ ipb,
                                              const float* __restrict__ cw) {
    int blk = blockIdx.x;
    int tid = threadIdx.x;
    if (blk < 64) {
        __shared__ float sWd[Ec];
        int b = blk >> 3, part = blk & 7;
        float mn = __uint_as_float(g_mnU[b]);
        float mx = __uint_as_float(g_mxU[b]);
        float inv = __fdividef(1.f, mx - mn + EPSc);
        for (int e = tid; e < Ec; e += 256) {
            float v = (g_msum[b * Ec + e] - mn) * inv;
            sWd[e] = W[e] * (1.f + LAMc * v);
        }
        __syncthreads();
        int s0 = part * 125;
        for (int e = s0 + tid; e < s0 + 125; e += 256)
            g_Wd[b * Ec + e] = __fdividef(sWd[e], (float)g_edge_cnt[e]);  // Wd/De
        for (int n = s0 + tid; n < s0 + 125; n += 256) {
            int d = g_node_deg[n];
            const int* L = g_node_edges + n * MAXD;
            float s = 0.f;
            for (int i = 0; i < d; i++) s += sWd[L[i]];
            g_dvi[b * Nc + n] = rsqrtf(fmaxf(s, EPSc));
        }
    } else {
        for (int it = tid; it < F_INc * DMc; it += 256) {
            int k = it >> 5, j = it & 31;
            float s = 0.f;
            #pragma unroll
            for (int f = 0; f < DMc; f++) s += ipw[k * DMc + f] * cw[f * HCc + j];
            g_ipwc[it] = s;
        }
        if (tid < 32) {
            float sb = 0.f;
            #pragma unroll
            for (int f = 0; f < DMc; f++) sb += ipb[f] * cw[f * HCc + tid];
            g_ipbc[tid] = sb;
        }
    }
}

// ---------------- T_n = (A @ 1)_n per batch: block per b ----------------
__global__ __launch_bounds__(1024) void k_tn() {
    __shared__ float sdvi[Nc + 1];
    __shared__ float sSDW[Ec + 1];
    int b = blockIdx.x;
    int tid = threadIdx.x;
    if (tid <= Nc) sdvi[tid] = (tid < Nc) ? g_dvi[b * Nc + tid] : 0.f;
    __syncthreads();
    if (tid < Ec) {
        const int* L = g_edge_nodes + tid * ESTRIDE;
        float s = 0.f;
        #pragma unroll
        for (int k = 0; k < ESTRIDE; k++) s += sdvi[L[k]];   // dummy idx Nc -> 0
        sSDW[tid] = s * g_Wd[b * Ec + tid];                  // (Wd/De) * SD_e
    }
    if (tid == Ec) sSDW[Ec] = 0.f;
    __syncthreads();
    if (tid < Nc) {
        int d = g_node_deg[tid];
        int d8 = (d + 7) & ~7;
        const int* L = g_node_edges + tid * MAXD;
        float s = 0.f;
        for (int i = 0; i < d8; i++) s += sSDW[L[i]];        // pad idx Ec -> 0
        g_T[b * Nc + tid] = sdvi[tid] * s;
    }
}

// ---------------- slice3: 16-dim gathers + deferred projection; block per (b,t) ----------------
__global__ __launch_bounds__(512, 2) void k_slice3(const float* __restrict__ x,
                                                   const float* __restrict__ cbg) {
    extern __shared__ float xs[];          // (Nc+1)*16, reused for edge features
    float* sP  = xs + (Nc + 1) * 16;       // 512: folded projection ipwc [k*32+j]
    float* sbb = sP + 512;                 // 32
    float* scb = sbb + 32;                 // 32
    int bt = blockIdx.x;
    int b = bt / Tc;
    int t = bt % Tc;
    int tid = threadIdx.x;
    int lane = tid & 31, w = tid >> 5;
    int fl = lane & 15;
    int sel = lane >> 4;

    if (tid < 512) sP[tid] = g_ipwc[tid];
    if (tid < 32) { sbb[tid] = g_ipbc[tid]; scb[tid] = cbg[tid]; }

    // phase A: q_n = dvi_n * x_n  (16-dim; NO projection yet)
    const float4* xb4 = (const float4*)(x + (size_t)bt * Nc * F_INc);
    for (int i = tid; i < (Nc + 1) * 4; i += 512) {
        int n = i >> 2, q = i & 3;
        float4 v = make_float4(0.f, 0.f, 0.f, 0.f);
        if (n < Nc) {
            float d = g_dvi[b * Nc + n];
            float4 xv = xb4[n * 4 + q];
            v = make_float4(xv.x * d, xv.y * d, xv.z * d, xv.w * d);
        }
        *(float4*)(xs + n * 16 + q * 4) = v;
    }
    __syncthreads();

    // phase B: edge gather into registers (warp w: edges [w*64, w*64+64) as 32 pairs)
    int e_base = w * 64;
    float u_reg[32];
    #pragma unroll
    for (int s = 0; s < 32; s++) {
        int e = e_base + 2 * s + sel;
        float uv = 0.f;
        if (e < Ec) {
            const int4* ip = (const int4*)(g_edge_nodes + e * ESTRIDE);
            int4 a0 = ip[0], a1 = ip[1], a2 = ip[2], a3 = ip[3], a4 = ip[4], a5 = ip[5];
            float p0 = xs[a0.x * 16 + fl] + xs[a1.x * 16 + fl]
                     + xs[a2.x * 16 + fl] + xs[a3.x * 16 + fl]
                     + xs[a4.x * 16 + fl] + xs[a5.x * 16 + fl];
            float p1 = xs[a0.y * 16 + fl] + xs[a1.y * 16 + fl]
                     + xs[a2.y * 16 + fl] + xs[a3.y * 16 + fl]
                     + xs[a4.y * 16 + fl] + xs[a5.y * 16 + fl];
            float p2 = xs[a0.z * 16 + fl] + xs[a1.z * 16 + fl]
                     + xs[a2.z * 16 + fl] + xs[a3.z * 16 + fl]
                     + xs[a4.z * 16 + fl] + xs[a5.z * 16 + fl];
            float p3 = xs[a0.w * 16 + fl] + xs[a1.w * 16 + fl]
                     + xs[a2.w * 16 + fl] + xs[a3.w * 16 + fl]
                     + xs[a4.w * 16 + fl] + xs[a5.w * 16 + fl];
            uv = ((p0 + p1) + (p2 + p3)) * g_Wd[b * Ec + e];
        }
        u_reg[s] = uv;
    }
    __syncthreads();   // all reads of q complete

    // phase C: overwrite smem with 16-dim edge features (+ dummy zero row 1000)
    #pragma unroll
    for (int s = 0; s < 32; s++) {
        int e = e_base + 2 * s + sel;
        if (e < Ec) xs[e * 16 + fl] = u_reg[s];
    }
    if (tid < 16) xs[Nc * 16 + tid] = 0.f;
    __syncthreads();

    // phase D: node gather (16-dim) -> project 16->32 -> + T*bb + cb -> silu -> g_hc
    for (int np = w; np < Nc / 2; np += 16) {
        int n = np * 2 + sel;
        int deg = g_node_deg[n];
        int d8 = (deg + 7) & ~7;
        const int* L = g_node_edges + n * MAXD;
        float p0 = 0.f, p1 = 0.f;
        for (int k = 0; k < d8; k += 8) {
            int4 a = *(const int4*)(L + k);
            int4 b2 = *(const int4*)(L + k + 4);
            p0 += xs[a.x * 16 + fl] + xs[a.z * 16 + fl]
                + xs[b2.x * 16 + fl] + xs[b2.z * 16 + fl];
            p1 += xs[a.y * 16 + fl] + xs[a.w * 16 + fl]
                + xs[b2.y * 16 + fl] + xs[b2.w * 16 + fl];
        }
        float Hv = (p0 + p1) * g_dvi[b * Nc + n];
        // projection: lanes 0-15 hold H for node n0=2np, lanes 16-31 for n1=2np+1
        int n0 = np * 2, n1 = np * 2 + 1;
        float z0 = g_T[b * Nc + n0] * sbb[lane] + scb[lane];
        float z1 = g_T[b * Nc + n1] * sbb[lane] + scb[lane];
        #pragma unroll
        for (int k = 0; k < 16; k++) {
            float h0 = __shfl_sync(FULLMASK, Hv, k);
            float h1 = __shfl_sync(FULLMASK, Hv, 16 + k);
            float pk = sP[k * 32 + lane];
            z0 += h0 * pk;
            z1 += h1 * pk;
        }
        g_hc[((size_t)(b * Nc + n0) * Tc + t) * 32 + lane] = silu_t(z0);
        g_hc[((size_t)(b * Nc + n1) * Tc + t) * 32 + lane] = silu_t(z1);
    }
}

// ---------------- LSTM: tensor-core recurrence (tf32 2-pass split), 16 rows/block ----------------
#define ASTR 68
#define ZSTR 132
__global__ __launch_bounds__(128) void k_lstm_tc(
    const float* __restrict__ wx, const float* __restrict__ wh,
    const float* __restrict__ lb,
    const float* __restrict__ hw1, const float* __restrict__ hb1,
    const float* __restrict__ hw2, const float* __restrict__ hb2,
    float* __restrict__ out, int Pout) {
    extern __shared__ __align__(16) float sm[];
    float* sAhi = sm;                    // 16*68 = 1088
    float* sAlo = sAhi + 16 * ASTR;      // 1088
    float* zbuf = sAlo + 16 * ASTR;      // 16*132 = 2112
    float* lbS  = zbuf + 16 * ZSTR;      // 128
    float* hw1S = lbS + 128;             // 1024
    float* hb1S = hw1S + 1024;           // 32
    float* hw2S = hb1S + 32;             // 384
    float* hb2S = hw2S + 384;            // 16

    int tid = threadIdx.x;
    int lane = tid & 31, w = tid >> 5;
    int gid = lane >> 2, tig = lane & 3;
    int gblk = w;
    int rb = blockIdx.x * 16;

    for (int i = tid; i < 1024; i += 128) hw1S[i] = hw1[i];
    for (int i = tid; i < 384; i += 128) hw2S[i] = hw2[i];
    if (tid < 128) lbS[tid] = lb[tid];
    if (tid < 32) hb1S[tid] = hb1[tid];
    if (tid < PREDc) hb2S[tid] = hb2[tid];

    u32 bw0[8][4], bw1[8][4];
    #pragma unroll
    for (int ks = 0; ks < 8; ks++) {
        #pragma unroll
        for (int nt = 0; nt < 4; nt++) {
            int col = gblk * 32 + nt * 8 + gid;
            int k0 = ks * 8 + tig;
            int k1 = k0 + 4;
            float f0 = (k0 < 32) ? wx[k0 * 128 + col] : wh[(k0 - 32) * 128 + col];
            float f1 = (k1 < 32) ? wx[k1 * 128 + col] : wh[(k1 - 32) * 128 + col];
            bw0[ks][nt] = tf32_of(f0);
            bw1[ks][nt] = tf32_of(f1);
        }
    }

    int r0 = w * 4;
    float h[4], cst[4];
    #pragma unroll
    for (int q = 0; q < 4; q++) {
        h[q] = 0.f; cst[q] = 0.f;
        int r = r0 + q;
        float hc = g_hc[((size_t)(rb + r) * Tc) * 32 + lane];
        u32 hib = tf32_of(hc);
        float hif = __uint_as_float(hib);
        sAhi[r * ASTR + lane] = hif;
        sAlo[r * ASTR + lane] = hc - hif;
        sAhi[r * ASTR + 32 + lane] = 0.f;
        sAlo[r * ASTR + 32 + lane] = 0.f;
    }
    __syncthreads();

    for (int t = 0; t < Tc; t++) {
        float hcn[4];
        if (t + 1 < Tc) {
            #pragma unroll
            for (int q = 0; q < 4; q++)
                hcn[q] = g_hc[((size_t)(rb + r0 + q) * Tc + t + 1) * 32 + lane];
        }

        float cc[4][4];
        #pragma unroll
        for (int nt = 0; nt < 4; nt++) {
            int col = gblk * 32 + nt * 8 + tig * 2;
            cc[nt][0] = lbS[col];
            cc[nt][1] = lbS[col + 1];
            cc[nt][2] = lbS[col];
            cc[nt][3] = lbS[col + 1];
        }
        #pragma unroll
        for (int ks = 0; ks < 8; ks++) {
            int ca = ks * 8 + tig;
            u32 a0h = __float_as_uint(sAhi[gid * ASTR + ca]);
            u32 a1h = __float_as_uint(sAhi[(gid + 8) * ASTR + ca]);
            u32 a2h = __float_as_uint(sAhi[gid * ASTR + ca + 4]);
            u32 a3h = __float_as_uint(sAhi[(gid + 8) * ASTR + ca + 4]);
            u32 a0l = __float_as_uint(sAlo[gid * ASTR + ca]);
            u32 a1l = __float_as_uint(sAlo[(gid + 8) * ASTR + ca]);
            u32 a2l = __float_as_uint(sAlo[gid * ASTR + ca + 4]);
            u32 a3l = __float_as_uint(sAlo[(gid + 8) * ASTR + ca + 4]);
            #pragma unroll
            for (int nt = 0; nt < 4; nt++) {
                mma_tf32(cc[nt], a0h, a1h, a2h, a3h, bw0[ks][nt], bw1[ks][nt]);
                mma_tf32(cc[nt], a0l, a1l, a2l, a3l, bw0[ks][nt], bw1[ks][nt]);
            }
        }
        #pragma unroll
        for (int nt = 0; nt < 4; nt++) {
            int col = gblk * 32 + nt * 8 + tig * 2;
            *(float2*)&zbuf[gid * ZSTR + col] = make_float2(cc[nt][0], cc[nt][1]);
            *(float2*)&zbuf[(gid + 8) * ZSTR + col] = make_float2(cc[nt][2], cc[nt][3]);
        }
        __syncthreads();

        #pragma unroll
        for (int q = 0; q < 4; q++) {
            int r = r0 + q;
            float zi = zbuf[r * ZSTR + lane];
            float zf = zbuf[r * ZSTR + 32 + lane];
            float zg = zbuf[r * ZSTR + 64 + lane];
            float zo = zbuf[r * ZSTR + 96 + lane];
            float ig = sigm_t(zi);
            float fg = sigm_t(zf);
            float gg = tanha(zg);
            float og = sigm_t(zo);
            cst[q] = fg * cst[q] + ig * gg;
            h[q] = og * tanha(cst[q]);
            u32 hib = tf32_of(h[q]);
            float hif = __uint_as_float(hib);
            sAhi[r * ASTR + 32 + lane] = hif;
            sAlo[r * ASTR + 32 + lane] = h[q] - hif;
            if (t + 1 < Tc) {
                float hc = hcn[q];
                u32 cb2 = tf32_of(hc);
                float cf2 = __uint_as_float(cb2);
                sAhi[r * ASTR + lane] = cf2;
                sAlo[r * ASTR + lane] = hc - cf2;
            }
        }
        __syncthreads();
    }

    // head: y = silu(h @ hw1 + hb1) @ hw2 + hb2   (warp owns rows r0..r0+4)
    #pragma unroll
    for (int q = 0; q < 4; q++) {
        int row = rb + r0 + q;
        int b = row / Nc;
        int n = row % Nc;
        float a = hb1S[lane];
        #pragma unroll 8
        for (int i = 0; i < 32; i++) {
            float hi = __shfl_sync(FULLMASK, h[q], i);
            a += hi * hw1S[i * 32 + lane];
        }
        float y1 = silu_t(a);
        float o = (lane < PREDc) ? hb2S[lane] : 0.f;
        #pragma unroll 8
        for (int j = 0; j < 32; j++) {
            float yj = __shfl_sync(FULLMASK, y1, j);
            if (lane < PREDc) o += yj * hw2S[j * PREDc + lane];
        }
        if (lane < Pout) out[((size_t)b * Pout + lane) * Nc + n] = o;
    }

    // tail: re-zero node degrees for the next run's edge-list build
    if (blockIdx.x < 8) {
        int i = blockIdx.x * 128 + tid;
        if (i < Nc) g_node_deg[i] = 0;
    }
}

// ---------------- launch ----------------
extern "C" void kernel_launch(void* const* d_in, const int* in_sizes, int n_in,
                              void* d_out, int out_size) {
    const float* x       = (const float*)d_in[0];
    const float* xraw    = (const float*)d_in[1];
    const float* W       = (const float*)d_in[3];
    const int*   members = (const int*)d_in[4];
    const int*   centers = (const int*)d_in[5];
    const int*   offsets = (const int*)d_in[6];
    const float* ipw     = (const float*)d_in[7];
    const float* ipb     = (const float*)d_in[8];
    const float* cw      = (const float*)d_in[9];
    const float* cb      = (const float*)d_in[10];
    const float* wx      = (const float*)d_in[11];
    const float* wh      = (const float*)d_in[12];
    const float* lb      = (const float*)d_in[13];
    const float* hw1     = (const float*)d_in[14];
    const float* hb1     = (const float*)d_in[15];
    const float* hw2     = (const float*)d_in[16];
    const float* hb2     = (const float*)d_in[17];
    float* out = (float*)d_out;
    int Pout = out_size / (Bc * Nc);

    int smem_slice = ((Nc + 1) * 16 + 512 + 32 + 32) * sizeof(float);                  // 66368
    int smem_lstm  = (16 * ASTR * 2 + 16 * ZSTR + 128 + 1024 + 32 + 384 + 16) * 4;     // ~23.5KB
    cudaFuncSetAttribute(k_slice3, cudaFuncAttributeMaxDynamicSharedMemorySize, smem_slice);
    cudaFuncSetAttribute(k_lstm_tc, cudaFuncAttributeMaxDynamicSharedMemorySize, smem_lstm);

    k_feat_build<<<254, 256>>>(xraw, members, centers, offsets);  // feat + build + minmax init
    k_sim_sort<<<1004, 256>>>(members, centers, offsets);         // sim + minmax + sort
    k_wdf2<<<65, 256>>>(W, ipw, ipb, cw);
    k_tn<<<Bc, 1024>>>();
    k_slice3<<<Bc * Tc, 512, smem_slice>>>(x, cb);
    k_lstm_tc<<<Bc * Nc / 16, 128, smem_lstm>>>(wx, wh, lb, hw1, hb1, hw2, hb2, out, Pout);
}